// round 1
// baseline (speedup 1.0000x reference)
#include <cuda_runtime.h>
#include <math.h>

// ---------------------------------------------------------------------------
// Problem constants
//   B=8, S=1024, D=1024, H=16, DK=64, NUM_BUCKETS=32, MAX_DIST=128
// ---------------------------------------------------------------------------
#define BB   8
#define SS   1024
#define DD   1024
#define HH   16
#define DK   64

// Scratch (static __device__ arrays — allocation-free per harness rules)
__device__ float g_q[BB * HH * SS * DK];     // [B,H,S,DK]
__device__ float g_k[BB * HH * SS * DK];
__device__ float g_v[BB * HH * SS * DK];
__device__ float g_ctx[BB * SS * HH * DK];   // [B,S,H*DK]
__device__ float g_bias[HH * (2 * SS - 1)];  // bias[h][d+1023], d = k-q

// ---------------------------------------------------------------------------
// T5 relative position bucket -> bias table
// For n >= 8:  floor(8*log(n/8)/log(16)) == floor(log2(n*n)) - 6  (exact)
// ---------------------------------------------------------------------------
__global__ void bias_kernel(const float* __restrict__ rel_emb) {
    int idx = blockIdx.x * blockDim.x + threadIdx.x;
    const int TAB = 2 * SS - 1;  // 2047
    if (idx >= HH * TAB) return;
    int h   = idx / TAB;
    int pos = idx % TAB;
    int d   = pos - (SS - 1);    // relative_position = k - q
    int n   = -d;                // q - k
    int ret = 0;
    if (n < 0) { ret = 16; n = -n; }
    int v;
    if (n < 8) {
        v = n;
    } else {
        int j = (31 - __clz(n * n)) - 6;   // floor(log2(n^2)) - 6
        v = 8 + j;
        if (v > 15) v = 15;
    }
    g_bias[idx] = rel_emb[(ret + v) * HH + h];
}

// ---------------------------------------------------------------------------
// SGEMM: C[M,N] = A[M,K] * B[K,N], fp32, M=8192, K=N=1024.
// 128x128 block tile, BK=8, 256 threads, 8x8 per-thread microtile,
// double-buffered shared memory with register prefetch.
// MODE 0: plain row-major output.
// MODE 1: output scattered to [B,H,S,DK] layout (QKV projections).
// ---------------------------------------------------------------------------
template <int MODE>
__global__ __launch_bounds__(256)
void sgemm_kernel(const float* __restrict__ A,
                  const float* __restrict__ Bm,
                  float* __restrict__ out) {
    __shared__ __align__(16) float As[2][8][132];
    __shared__ __align__(16) float Bs[2][8][128];

    const int K = 1024, N = 1024;
    const int tid = threadIdx.x;
    const int tx = tid & 15, ty = tid >> 4;
    const int bx = blockIdx.x, by = blockIdx.y;

    const float* Aptr = A + (by * 128 + (tid >> 1)) * K + (tid & 1) * 4;
    const float* Bptr = Bm + (tid >> 5) * N + bx * 128 + (tid & 31) * 4;
    const int ak = (tid & 1) * 4;
    const int am = tid >> 1;
    const int bk = tid >> 5;
    const int bn = (tid & 31) * 4;

    // stage 0
    float4 ra = *(const float4*)Aptr;
    float4 rb = *(const float4*)Bptr;
    As[0][ak + 0][am] = ra.x;
    As[0][ak + 1][am] = ra.y;
    As[0][ak + 2][am] = ra.z;
    As[0][ak + 3][am] = ra.w;
    *(float4*)&Bs[0][bk][bn] = rb;
    __syncthreads();

    float c[8][8];
#pragma unroll
    for (int i = 0; i < 8; ++i)
#pragma unroll
        for (int j = 0; j < 8; ++j) c[i][j] = 0.0f;

    const int NT = K / 8;  // 128
    for (int t = 0; t < NT; ++t) {
        const int cur = t & 1;
        if (t + 1 < NT) {
            ra = *(const float4*)(Aptr + (t + 1) * 8);
            rb = *(const float4*)(Bptr + (t + 1) * 8 * N);
        }
#pragma unroll
        for (int kk = 0; kk < 8; ++kk) {
            float a[8], b[8];
            *(float4*)&a[0] = *(const float4*)&As[cur][kk][ty * 8];
            *(float4*)&a[4] = *(const float4*)&As[cur][kk][ty * 8 + 4];
            *(float4*)&b[0] = *(const float4*)&Bs[cur][kk][tx * 8];
            *(float4*)&b[4] = *(const float4*)&Bs[cur][kk][tx * 8 + 4];
#pragma unroll
            for (int i = 0; i < 8; ++i)
#pragma unroll
                for (int j = 0; j < 8; ++j) c[i][j] += a[i] * b[j];
        }
        if (t + 1 < NT) {
            const int nxt = cur ^ 1;
            As[nxt][ak + 0][am] = ra.x;
            As[nxt][ak + 1][am] = ra.y;
            As[nxt][ak + 2][am] = ra.z;
            As[nxt][ak + 3][am] = ra.w;
            *(float4*)&Bs[nxt][bk][bn] = rb;
            __syncthreads();
        }
    }

    const int r0 = by * 128 + ty * 8;
    const int c0 = bx * 128 + tx * 8;
#pragma unroll
    for (int i = 0; i < 8; ++i) {
#pragma unroll
        for (int j4 = 0; j4 < 8; j4 += 4) {
            float4 val = make_float4(c[i][j4], c[i][j4 + 1], c[i][j4 + 2], c[i][j4 + 3]);
            if (MODE == 0) {
                *(float4*)&out[(r0 + i) * N + c0 + j4] = val;
            } else {
                const int r = r0 + i;
                const int b = r >> 10, s = r & 1023;
                const int cc = c0 + j4;
                const int h = cc >> 6, d = cc & 63;
                *(float4*)&out[(((b << 4) + h) * 1024 + s) * 64 + d] = val;
            }
        }
    }
}

// ---------------------------------------------------------------------------
// Flash attention, fp32, one block per (q-tile=64, h, b).
// 256 threads as 16x16: thread (ty,tx) owns 4 q-rows x 4 dk-cols.
// Online softmax; bias added from precomputed table slice in smem.
// Shared: Qs[64][68], Kt[64][68] ([dk][k]), Vs[64][68], Ps[64][68], bias[1088]
// ---------------------------------------------------------------------------
#define LD 68
#define ATT_SMEM_FLOATS (4 * 64 * LD + 1088)

__global__ __launch_bounds__(256, 2)
void attn_kernel() {
    extern __shared__ __align__(16) float sm[];
    float* Qs = sm;
    float* Kt = Qs + 64 * LD;
    float* Vs = Kt + 64 * LD;
    float* Ps = Vs + 64 * LD;
    float* bs = Ps + 64 * LD;

    const int tid = threadIdx.x;
    const int tx = tid & 15, ty = tid >> 4;
    const int tx4 = tx * 4, ty4 = ty * 4;
    const int qt = blockIdx.x, h = blockIdx.y, b = blockIdx.z;
    const int q0 = qt * 64;

    const float* Qg = g_q + (size_t)(b * HH + h) * SS * DK;
    const float* Kg = g_k + (size_t)(b * HH + h) * SS * DK;
    const float* Vg = g_v + (size_t)(b * HH + h) * SS * DK;

    // Load Q tile [64][64]
    {
        const int r = tid >> 2;
        const int cb = (tid & 3) * 16;
        const float* src = Qg + (q0 + r) * DK + cb;
        float* dst = Qs + r * LD + cb;
#pragma unroll
        for (int u = 0; u < 16; u += 4)
            *(float4*)&dst[u] = *(const float4*)&src[u];
    }
    // Load bias slice: bs[t] = g_bias[h][960 - q0 + t], t in [0,1087)
    {
        const float* bsrc = g_bias + h * (2 * SS - 1) + ((SS - 1) - q0 - 63);
        for (int i = tid; i < 1087; i += 256) bs[i] = bsrc[i];
    }

    float o[4][4];
#pragma unroll
    for (int i = 0; i < 4; ++i)
#pragma unroll
        for (int j = 0; j < 4; ++j) o[i][j] = 0.0f;
    float m_i[4] = {-1e30f, -1e30f, -1e30f, -1e30f};
    float l_i[4] = {0.0f, 0.0f, 0.0f, 0.0f};

    for (int kt = 0; kt < SS / 64; ++kt) {
        const int k0 = kt * 64;
        __syncthreads();
        // Load K (transposed -> Kt[d][k]) and V (natural Vs[k][d])
        {
            const int r = tid >> 2;            // k row 0..63
            const int cb = (tid & 3) * 16;     // d col base
            const float* ks = Kg + (k0 + r) * DK + cb;
            const float* vsp = Vg + (k0 + r) * DK + cb;
#pragma unroll
            for (int u = 0; u < 16; u += 4) {
                float4 kv = *(const float4*)&ks[u];
                Kt[(cb + u + 0) * LD + r] = kv.x;
                Kt[(cb + u + 1) * LD + r] = kv.y;
                Kt[(cb + u + 2) * LD + r] = kv.z;
                Kt[(cb + u + 3) * LD + r] = kv.w;
                *(float4*)&Vs[r * LD + cb + u] = *(const float4*)&vsp[u];
            }
        }
        __syncthreads();

        // S = Q @ K^T  (4x4 per thread)
        float s[4][4];
#pragma unroll
        for (int i = 0; i < 4; ++i)
#pragma unroll
            for (int j = 0; j < 4; ++j) s[i][j] = 0.0f;

#pragma unroll
        for (int kk = 0; kk < 64; kk += 4) {
            float q[4][4];
#pragma unroll
            for (int i = 0; i < 4; ++i)
                *(float4*)&q[i][0] = *(const float4*)&Qs[(ty4 + i) * LD + kk];
#pragma unroll
            for (int cc = 0; cc < 4; ++cc) {
                float4 kv = *(const float4*)&Kt[(kk + cc) * LD + tx4];
                float kb[4] = {kv.x, kv.y, kv.z, kv.w};
#pragma unroll
                for (int i = 0; i < 4; ++i)
#pragma unroll
                    for (int j = 0; j < 4; ++j) s[i][j] += q[i][cc] * kb[j];
            }
        }

        // bias + online softmax (row stats replicated across the 16 tx lanes)
#pragma unroll
        for (int i = 0; i < 4; ++i) {
#pragma unroll
            for (int j = 0; j < 4; ++j)
                s[i][j] += bs[k0 + tx4 + j + 63 - (ty4 + i)];

            float mt = fmaxf(fmaxf(s[i][0], s[i][1]), fmaxf(s[i][2], s[i][3]));
#pragma unroll
            for (int off = 8; off; off >>= 1)
                mt = fmaxf(mt, __shfl_xor_sync(0xffffffffu, mt, off));
            const float mn = fmaxf(m_i[i], mt);
            const float al = __expf(m_i[i] - mn);
            float p0 = __expf(s[i][0] - mn);
            float p1 = __expf(s[i][1] - mn);
            float p2 = __expf(s[i][2] - mn);
            float p3 = __expf(s[i][3] - mn);
            float rs = (p0 + p1) + (p2 + p3);
#pragma unroll
            for (int off = 8; off; off >>= 1)
                rs += __shfl_xor_sync(0xffffffffu, rs, off);
            l_i[i] = l_i[i] * al + rs;
            m_i[i] = mn;
#pragma unroll
            for (int j = 0; j < 4; ++j) o[i][j] *= al;
            *(float4*)&Ps[(ty4 + i) * LD + tx4] = make_float4(p0, p1, p2, p3);
        }
        __syncthreads();

        // O += P @ V
#pragma unroll
        for (int kc = 0; kc < 64; kc += 4) {
            float p[4][4];
#pragma unroll
            for (int i = 0; i < 4; ++i)
                *(float4*)&p[i][0] = *(const float4*)&Ps[(ty4 + i) * LD + kc];
#pragma unroll
            for (int cc = 0; cc < 4; ++cc) {
                float4 vv = *(const float4*)&Vs[(kc + cc) * LD + tx4];
                float vb[4] = {vv.x, vv.y, vv.z, vv.w};
#pragma unroll
                for (int i = 0; i < 4; ++i)
#pragma unroll
                    for (int j = 0; j < 4; ++j) o[i][j] += p[i][cc] * vb[j];
            }
        }
    }

    // Write context [B,S,H*DK]
#pragma unroll
    for (int i = 0; i < 4; ++i) {
        const float inv = 1.0f / l_i[i];
        const int r = b * SS + q0 + ty4 + i;
        float4 val = make_float4(o[i][0] * inv, o[i][1] * inv,
                                 o[i][2] * inv, o[i][3] * inv);
        *(float4*)&g_ctx[(size_t)r * (HH * DK) + h * DK + tx4] = val;
    }
}

// ---------------------------------------------------------------------------
// Launch
// ---------------------------------------------------------------------------
extern "C" void kernel_launch(void* const* d_in, const int* in_sizes, int n_in,
                              void* d_out, int out_size) {
    const float* x   = (const float*)d_in[0];
    const float* Wq  = (const float*)d_in[1];
    const float* Wk  = (const float*)d_in[2];
    const float* Wv  = (const float*)d_in[3];
    const float* Wo  = (const float*)d_in[4];
    const float* rel = (const float*)d_in[5];
    float* out = (float*)d_out;

    float *pq, *pk, *pv, *pctx;
    cudaGetSymbolAddress((void**)&pq, g_q);
    cudaGetSymbolAddress((void**)&pk, g_k);
    cudaGetSymbolAddress((void**)&pv, g_v);
    cudaGetSymbolAddress((void**)&pctx, g_ctx);

    // 1) bias table
    bias_kernel<<<(HH * (2 * SS - 1) + 255) / 256, 256>>>(rel);

    // 2) QKV projections -> [B,H,S,DK]
    dim3 gemm_grid(DD / 128, (BB * SS) / 128);  // (8, 64)
    sgemm_kernel<1><<<gemm_grid, 256>>>(x, Wq, pq);
    sgemm_kernel<1><<<gemm_grid, 256>>>(x, Wk, pk);
    sgemm_kernel<1><<<gemm_grid, 256>>>(x, Wv, pv);

    // 3) flash attention -> g_ctx [B,S,H*DK]
    const int att_smem = ATT_SMEM_FLOATS * (int)sizeof(float);
    cudaFuncSetAttribute(attn_kernel,
                         cudaFuncAttributeMaxDynamicSharedMemorySize, att_smem);
    dim3 attn_grid(SS / 64, HH, BB);  // (16, 16, 8)
    attn_kernel<<<attn_grid, 256, att_smem>>>();

    // 4) output projection
    sgemm_kernel<0><<<gemm_grid, 256>>>(pctx, Wo, out);
}

// round 3
// speedup vs baseline: 1.3231x; 1.3231x over previous
#include <cuda_runtime.h>
#include <cuda_bf16.h>
#include <math.h>
#include <stdint.h>

// ---------------------------------------------------------------------------
// Problem constants: B=8, S=1024, D=1024, H=16, DK=64, BUCKETS=32, MAXDIST=128
// ---------------------------------------------------------------------------
#define BB   8
#define SS   1024
#define DD   1024
#define HH   16
#define DK   64

__device__ __forceinline__ uint32_t smem_u32(const void* p) {
    uint32_t a;
    asm("{ .reg .u64 t; cvta.to.shared.u64 t, %1; cvt.u32.u64 %0, t; }"
        : "=r"(a) : "l"(p));
    return a;
}

#define CP_ASYNC16(dst, src) \
    asm volatile("cp.async.cg.shared.global [%0], [%1], 16;" :: "r"(dst), "l"(src))
#define CP_COMMIT() asm volatile("cp.async.commit_group;" ::: "memory")
#define CP_WAIT2()  asm volatile("cp.async.wait_group 2;" ::: "memory")

#define LDSM4(r, a)                                                          \
    asm volatile("ldmatrix.sync.aligned.m8n8.x4.shared.b16 {%0,%1,%2,%3}, [%4];" \
        : "=r"((r)[0]), "=r"((r)[1]), "=r"((r)[2]), "=r"((r)[3]) : "r"(a))

#define MMA16816(c, a, b)                                                    \
    asm volatile("mma.sync.aligned.m16n8k16.row.col.f32.bf16.bf16.f32 "      \
        "{%0,%1,%2,%3}, {%4,%5,%6,%7}, {%8,%9}, {%0,%1,%2,%3};"              \
        : "+f"((c)[0]), "+f"((c)[1]), "+f"((c)[2]), "+f"((c)[3])             \
        : "r"((a)[0]), "r"((a)[1]), "r"((a)[2]), "r"((a)[3]),                \
          "r"((b)[0]), "r"((b)[1]))

// ---------------------------------------------------------------------------
// Global scratch
// ---------------------------------------------------------------------------
__device__ float g_q[BB * HH * SS * DK];
__device__ float g_k[BB * HH * SS * DK];
__device__ float g_v[BB * HH * SS * DK];
__device__ float g_ctx[BB * SS * HH * DK];
__device__ float g_bias[HH * (2 * SS - 1)];
__device__ __nv_bfloat16 g_ahi[BB * SS * DD];
__device__ __nv_bfloat16 g_alo[BB * SS * DD];
__device__ __nv_bfloat16 g_wthi[DD * DD];
__device__ __nv_bfloat16 g_wtlo[DD * DD];

// ---------------------------------------------------------------------------
// Bias table (exact integer reduction of the T5 bucket function)
// ---------------------------------------------------------------------------
__global__ void bias_kernel(const float* __restrict__ rel_emb) {
    int idx = blockIdx.x * blockDim.x + threadIdx.x;
    const int TAB = 2 * SS - 1;
    if (idx >= HH * TAB) return;
    int h = idx / TAB, pos = idx % TAB;
    int n = -(pos - (SS - 1));
    int ret = 0;
    if (n < 0) { ret = 16; n = -n; }
    int v;
    if (n < 8) v = n;
    else {
        int j = (31 - __clz(n * n)) - 6;
        v = 8 + j;
        if (v > 15) v = 15;
    }
    g_bias[idx] = rel_emb[(ret + v) * HH + h];
}

// ---------------------------------------------------------------------------
// fp32 -> bf16 hi/lo split
// ---------------------------------------------------------------------------
__global__ void split_kernel(const float* __restrict__ src,
                             __nv_bfloat16* __restrict__ hi,
                             __nv_bfloat16* __restrict__ lo, int n4) {
    int i = blockIdx.x * blockDim.x + threadIdx.x;
    if (i >= n4) return;
    float4 v = ((const float4*)src)[i];
    __nv_bfloat16 h[4], l[4];
    float vv[4] = {v.x, v.y, v.z, v.w};
#pragma unroll
    for (int j = 0; j < 4; ++j) {
        h[j] = __float2bfloat16(vv[j]);
        l[j] = __float2bfloat16(vv[j] - __bfloat162float(h[j]));
    }
    *(uint2*)&hi[4 * i] = *(uint2*)h;
    *(uint2*)&lo[4 * i] = *(uint2*)l;
}

// ---------------------------------------------------------------------------
// Transpose+split: Wt[n][k] = split(W[k][n])
// ---------------------------------------------------------------------------
__global__ void splitT_kernel(const float* __restrict__ W,
                              __nv_bfloat16* __restrict__ hi,
                              __nv_bfloat16* __restrict__ lo) {
    __shared__ float t[32][33];
    const int tx = threadIdx.x, ty = threadIdx.y;
    const int bx = blockIdx.x, by = blockIdx.y;
#pragma unroll
    for (int j = 0; j < 32; j += 8)
        t[ty + j][tx] = W[(by * 32 + ty + j) * DD + bx * 32 + tx];
    __syncthreads();
#pragma unroll
    for (int j = 0; j < 32; j += 8) {
        float v = t[tx][ty + j];
        __nv_bfloat16 h = __float2bfloat16(v);
        __nv_bfloat16 l = __float2bfloat16(v - __bfloat162float(h));
        int o = (bx * 32 + ty + j) * DD + by * 32 + tx;
        hi[o] = h;
        lo[o] = l;
    }
}

// ---------------------------------------------------------------------------
// bf16-split mma.sync GEMM: C[8192,1024] = A[8192,1024] @ Wt^T (fp32 acc)
//   Products: Ahi*Bhi + Alo*Bhi + Ahi*Blo  over 96 k32 iterations.
//   128x128 CTA tile, 8 warps (4 x 2), warp = 32x64 (2x8 m16n8k16 tiles).
//   Smem: 3 stages x (A 128x32 + B 128x32) bf16, rows padded to 40 bf16
//   (80 B) -> conflict-free ldmatrix; cp.async 3-deep pipeline.
//   MODE 0: row-major out.  MODE 1: scatter to [B,H,S,DK].
// ---------------------------------------------------------------------------
#define ROWB   80                       // padded row bytes (40 bf16)
#define AT_B   (128 * ROWB)             // 10240
#define STG_B  (2 * AT_B)               // 20480 per stage (A + B)
#define GEMM_SMEM (3 * STG_B)           // 61440

template <int MODE>
__global__ __launch_bounds__(256, 2)
void tc_gemm(const __nv_bfloat16* __restrict__ Ahi,
             const __nv_bfloat16* __restrict__ Alo,
             const __nv_bfloat16* __restrict__ Bhi,
             const __nv_bfloat16* __restrict__ Blo,
             float* __restrict__ out) {
    extern __shared__ __align__(128) char smc[];
    const uint32_t sb = smem_u32(smc);
    const int tid = threadIdx.x;
    const int lane = tid & 31, wid = tid >> 5;
    const int m0 = blockIdx.y * 128, n0 = blockIdx.x * 128;

    // loader coords: thread -> (row, 32B pair) of a 128x64B tile
    const int lrow = tid >> 1;
    const int lsub = (tid & 1) * 32;    // byte offset within 64B row data

    // warp tile coords
    const int wm = (wid & 3) * 32;
    const int wn = (wid >> 2) * 64;
    // ldmatrix lane addresses (byte offsets within stage)
    const uint32_t aoff = (uint32_t)(wm + (lane & 15)) * ROWB + (lane >> 4) * 16;
    const uint32_t boff = AT_B +
        (uint32_t)(wn + (lane & 7) + (lane >> 4) * 8) * ROWB + ((lane >> 3) & 1) * 16;

    float c[2][8][4];
#pragma unroll
    for (int i = 0; i < 2; ++i)
#pragma unroll
        for (int j = 0; j < 8; ++j)
#pragma unroll
            for (int q = 0; q < 4; ++q) c[i][j][q] = 0.0f;

    const int NIT = 96;  // 3 products x 32 k-chunks

    // --- stage loader ---
    auto issue = [&](int t) {
        const int p = t >> 5;                 // product id
        const int kb = (t & 31) * 32;         // k base (elements)
        const __nv_bfloat16* Ap = (p == 1) ? Alo : Ahi;
        const __nv_bfloat16* Bp = (p == 2) ? Blo : Bhi;
        const uint32_t dstA = sb + (t % 3) * STG_B + lrow * ROWB + lsub;
        const uint32_t dstB = dstA + AT_B;
        const char* srcA = (const char*)(Ap + (size_t)(m0 + lrow) * DD + kb) + lsub;
        const char* srcB = (const char*)(Bp + (size_t)(n0 + lrow) * DD + kb) + lsub;
        CP_ASYNC16(dstA, srcA);
        CP_ASYNC16(dstA + 16, srcA + 16);
        CP_ASYNC16(dstB, srcB);
        CP_ASYNC16(dstB + 16, srcB + 16);
    };

    issue(0); CP_COMMIT();
    issue(1); CP_COMMIT();

    for (int t = 0; t < NIT; ++t) {
        if (t + 2 < NIT) issue(t + 2);
        CP_COMMIT();
        CP_WAIT2();
        __syncthreads();

        const uint32_t stg = sb + (t % 3) * STG_B;
#pragma unroll
        for (int s = 0; s < 2; ++s) {
            uint32_t ar[2][4], br[4][4];
#pragma unroll
            for (int mi = 0; mi < 2; ++mi)
                LDSM4(ar[mi], stg + aoff + mi * (16 * ROWB) + s * 32);
#pragma unroll
            for (int p = 0; p < 4; ++p)
                LDSM4(br[p], stg + boff + p * (16 * ROWB) + s * 32);
#pragma unroll
            for (int mi = 0; mi < 2; ++mi)
#pragma unroll
                for (int nj = 0; nj < 8; ++nj) {
                    uint32_t bf[2] = {br[nj >> 1][(nj & 1) * 2],
                                      br[nj >> 1][(nj & 1) * 2 + 1]};
                    MMA16816(c[mi][nj], ar[mi], bf);
                }
        }
        __syncthreads();
    }

    // epilogue
#pragma unroll
    for (int mi = 0; mi < 2; ++mi) {
#pragma unroll
        for (int nj = 0; nj < 8; ++nj) {
            const int col = n0 + wn + nj * 8 + (lane & 3) * 2;
            const int r = m0 + wm + mi * 16 + (lane >> 2);
            float2 v0 = make_float2(c[mi][nj][0], c[mi][nj][1]);
            float2 v1 = make_float2(c[mi][nj][2], c[mi][nj][3]);
            if (MODE == 0) {
                *(float2*)&out[(size_t)r * DD + col] = v0;
                *(float2*)&out[(size_t)(r + 8) * DD + col] = v1;
            } else {
                const int h = col >> 6, d = col & 63;
                {
                    const int b = r >> 10, s2 = r & 1023;
                    *(float2*)&out[((size_t)((b << 4) + h) * 1024 + s2) * 64 + d] = v0;
                }
                {
                    const int r8 = r + 8;
                    const int b = r8 >> 10, s2 = r8 & 1023;
                    *(float2*)&out[((size_t)((b << 4) + h) * 1024 + s2) * 64 + d] = v1;
                }
            }
        }
    }
}

// ---------------------------------------------------------------------------
// Flash attention (fp32, unchanged from R1)
// ---------------------------------------------------------------------------
#define LD 68
#define ATT_SMEM_FLOATS (4 * 64 * LD + 1088)

__global__ __launch_bounds__(256, 2)
void attn_kernel() {
    extern __shared__ __align__(16) float smf[];
    float* Qs = smf;
    float* Kt = Qs + 64 * LD;
    float* Vs = Kt + 64 * LD;
    float* Ps = Vs + 64 * LD;
    float* bs = Ps + 64 * LD;

    const int tid = threadIdx.x;
    const int tx = tid & 15, ty = tid >> 4;
    const int tx4 = tx * 4, ty4 = ty * 4;
    const int qt = blockIdx.x, h = blockIdx.y, b = blockIdx.z;
    const int q0 = qt * 64;

    const float* Qg = g_q + (size_t)(b * HH + h) * SS * DK;
    const float* Kg = g_k + (size_t)(b * HH + h) * SS * DK;
    const float* Vg = g_v + (size_t)(b * HH + h) * SS * DK;

    {
        const int r = tid >> 2;
        const int cb = (tid & 3) * 16;
        const float* src = Qg + (q0 + r) * DK + cb;
        float* dst = Qs + r * LD + cb;
#pragma unroll
        for (int u = 0; u < 16; u += 4)
            *(float4*)&dst[u] = *(const float4*)&src[u];
    }
    {
        const float* bsrc = g_bias + h * (2 * SS - 1) + ((SS - 1) - q0 - 63);
        for (int i = tid; i < 1087; i += 256) bs[i] = bsrc[i];
    }

    float o[4][4];
#pragma unroll
    for (int i = 0; i < 4; ++i)
#pragma unroll
        for (int j = 0; j < 4; ++j) o[i][j] = 0.0f;
    float m_i[4] = {-1e30f, -1e30f, -1e30f, -1e30f};
    float l_i[4] = {0.0f, 0.0f, 0.0f, 0.0f};

    for (int kt = 0; kt < SS / 64; ++kt) {
        const int k0 = kt * 64;
        __syncthreads();
        {
            const int r = tid >> 2;
            const int cb = (tid & 3) * 16;
            const float* ks = Kg + (k0 + r) * DK + cb;
            const float* vsp = Vg + (k0 + r) * DK + cb;
#pragma unroll
            for (int u = 0; u < 16; u += 4) {
                float4 kv = *(const float4*)&ks[u];
                Kt[(cb + u + 0) * LD + r] = kv.x;
                Kt[(cb + u + 1) * LD + r] = kv.y;
                Kt[(cb + u + 2) * LD + r] = kv.z;
                Kt[(cb + u + 3) * LD + r] = kv.w;
                *(float4*)&Vs[r * LD + cb + u] = *(const float4*)&vsp[u];
            }
        }
        __syncthreads();

        float s[4][4];
#pragma unroll
        for (int i = 0; i < 4; ++i)
#pragma unroll
            for (int j = 0; j < 4; ++j) s[i][j] = 0.0f;

#pragma unroll
        for (int kk = 0; kk < 64; kk += 4) {
            float q[4][4];
#pragma unroll
            for (int i = 0; i < 4; ++i)
                *(float4*)&q[i][0] = *(const float4*)&Qs[(ty4 + i) * LD + kk];
#pragma unroll
            for (int cc = 0; cc < 4; ++cc) {
                float4 kv = *(const float4*)&Kt[(kk + cc) * LD + tx4];
                float kb[4] = {kv.x, kv.y, kv.z, kv.w};
#pragma unroll
                for (int i = 0; i < 4; ++i)
#pragma unroll
                    for (int j = 0; j < 4; ++j) s[i][j] += q[i][cc] * kb[j];
            }
        }

#pragma unroll
        for (int i = 0; i < 4; ++i) {
#pragma unroll
            for (int j = 0; j < 4; ++j)
                s[i][j] += bs[k0 + tx4 + j + 63 - (ty4 + i)];

            float mt = fmaxf(fmaxf(s[i][0], s[i][1]), fmaxf(s[i][2], s[i][3]));
#pragma unroll
            for (int off = 8; off; off >>= 1)
                mt = fmaxf(mt, __shfl_xor_sync(0xffffffffu, mt, off));
            const float mn = fmaxf(m_i[i], mt);
            const float al = __expf(m_i[i] - mn);
            float p0 = __expf(s[i][0] - mn);
            float p1 = __expf(s[i][1] - mn);
            float p2 = __expf(s[i][2] - mn);
            float p3 = __expf(s[i][3] - mn);
            float rs = (p0 + p1) + (p2 + p3);
#pragma unroll
            for (int off = 8; off; off >>= 1)
                rs += __shfl_xor_sync(0xffffffffu, rs, off);
            l_i[i] = l_i[i] * al + rs;
            m_i[i] = mn;
#pragma unroll
            for (int j = 0; j < 4; ++j) o[i][j] *= al;
            *(float4*)&Ps[(ty4 + i) * LD + tx4] = make_float4(p0, p1, p2, p3);
        }
        __syncthreads();

#pragma unroll
        for (int kc = 0; kc < 64; kc += 4) {
            float p[4][4];
#pragma unroll
            for (int i = 0; i < 4; ++i)
                *(float4*)&p[i][0] = *(const float4*)&Ps[(ty4 + i) * LD + kc];
#pragma unroll
            for (int cc = 0; cc < 4; ++cc) {
                float4 vv = *(const float4*)&Vs[(kc + cc) * LD + tx4];
                float vb[4] = {vv.x, vv.y, vv.z, vv.w};
#pragma unroll
                for (int i = 0; i < 4; ++i)
#pragma unroll
                    for (int j = 0; j < 4; ++j) o[i][j] += p[i][cc] * vb[j];
            }
        }
    }

#pragma unroll
    for (int i = 0; i < 4; ++i) {
        const float inv = 1.0f / l_i[i];
        const int r = b * SS + q0 + ty4 + i;
        float4 val = make_float4(o[i][0] * inv, o[i][1] * inv,
                                 o[i][2] * inv, o[i][3] * inv);
        *(float4*)&g_ctx[(size_t)r * (HH * DK) + h * DK + tx4] = val;
    }
}

// ---------------------------------------------------------------------------
// Launch
// ---------------------------------------------------------------------------
extern "C" void kernel_launch(void* const* d_in, const int* in_sizes, int n_in,
                              void* d_out, int out_size) {
    const float* x   = (const float*)d_in[0];
    const float* Wq  = (const float*)d_in[1];
    const float* Wk  = (const float*)d_in[2];
    const float* Wv  = (const float*)d_in[3];
    const float* Wo  = (const float*)d_in[4];
    const float* rel = (const float*)d_in[5];
    float* out = (float*)d_out;

    float *pq, *pk, *pv, *pctx;
    __nv_bfloat16 *pah, *pal, *pwh, *pwl;
    cudaGetSymbolAddress((void**)&pq, g_q);
    cudaGetSymbolAddress((void**)&pk, g_k);
    cudaGetSymbolAddress((void**)&pv, g_v);
    cudaGetSymbolAddress((void**)&pctx, g_ctx);
    cudaGetSymbolAddress((void**)&pah, g_ahi);
    cudaGetSymbolAddress((void**)&pal, g_alo);
    cudaGetSymbolAddress((void**)&pwh, g_wthi);
    cudaGetSymbolAddress((void**)&pwl, g_wtlo);

    static bool attr_set = false;
    if (!attr_set) {
        cudaFuncSetAttribute(tc_gemm<0>, cudaFuncAttributeMaxDynamicSharedMemorySize, GEMM_SMEM);
        cudaFuncSetAttribute(tc_gemm<1>, cudaFuncAttributeMaxDynamicSharedMemorySize, GEMM_SMEM);
        cudaFuncSetAttribute(attn_kernel, cudaFuncAttributeMaxDynamicSharedMemorySize,
                             ATT_SMEM_FLOATS * (int)sizeof(float));
        attr_set = true;
    }

    // 1) bias table
    bias_kernel<<<(HH * (2 * SS - 1) + 255) / 256, 256>>>(rel);

    // 2) split x
    const int n4 = BB * SS * DD / 4;
    split_kernel<<<(n4 + 255) / 256, 256>>>(x, pah, pal, n4);

    // 3) QKV projections
    dim3 tg(32, 32), tb(32, 8);
    dim3 gg(DD / 128, (BB * SS) / 128);  // (8, 64)
    splitT_kernel<<<tg, tb>>>(Wq, pwh, pwl);
    tc_gemm<1><<<gg, 256, GEMM_SMEM>>>(pah, pal, pwh, pwl, pq);
    splitT_kernel<<<tg, tb>>>(Wk, pwh, pwl);
    tc_gemm<1><<<gg, 256, GEMM_SMEM>>>(pah, pal, pwh, pwl, pk);
    splitT_kernel<<<tg, tb>>>(Wv, pwh, pwl);
    tc_gemm<1><<<gg, 256, GEMM_SMEM>>>(pah, pal, pwh, pwl, pv);

    // 4) attention
    const int att_smem = ATT_SMEM_FLOATS * (int)sizeof(float);
    dim3 ag(SS / 64, HH, BB);
    attn_kernel<<<ag, 256, att_smem>>>();

    // 5) output projection
    split_kernel<<<(n4 + 255) / 256, 256>>>(pctx, pah, pal, n4);
    splitT_kernel<<<tg, tb>>>(Wo, pwh, pwl);
    tc_gemm<0><<<gg, 256, GEMM_SMEM>>>(pah, pal, pwh, pwl, out);
}

// round 4
// speedup vs baseline: 2.5012x; 1.8904x over previous
#include <cuda_runtime.h>
#include <cuda_bf16.h>
#include <cuda_fp16.h>
#include <math.h>
#include <stdint.h>

#define BB   8
#define SS   1024
#define DD   1024
#define HH   16
#define DK   64

__device__ __forceinline__ uint32_t smem_u32(const void* p) {
    uint32_t a;
    asm("{ .reg .u64 t; cvta.to.shared.u64 t, %1; cvt.u32.u64 %0, t; }"
        : "=r"(a) : "l"(p));
    return a;
}

#define CP_ASYNC16(dst, src) \
    asm volatile("cp.async.cg.shared.global [%0], [%1], 16;" :: "r"(dst), "l"(src))
#define CP_COMMIT() asm volatile("cp.async.commit_group;" ::: "memory")
#define CP_WAIT0()  asm volatile("cp.async.wait_group 0;" ::: "memory")
#define CP_WAIT2()  asm volatile("cp.async.wait_group 2;" ::: "memory")

#define LDSM4(r, a)                                                          \
    asm volatile("ldmatrix.sync.aligned.m8n8.x4.shared.b16 {%0,%1,%2,%3}, [%4];" \
        : "=r"((r)[0]), "=r"((r)[1]), "=r"((r)[2]), "=r"((r)[3]) : "r"(a))
#define LDSM4T(r, a)                                                         \
    asm volatile("ldmatrix.sync.aligned.m8n8.x4.trans.shared.b16 {%0,%1,%2,%3}, [%4];" \
        : "=r"((r)[0]), "=r"((r)[1]), "=r"((r)[2]), "=r"((r)[3]) : "r"(a))

#define MMA_BF16(c, a, b)                                                    \
    asm volatile("mma.sync.aligned.m16n8k16.row.col.f32.bf16.bf16.f32 "      \
        "{%0,%1,%2,%3}, {%4,%5,%6,%7}, {%8,%9}, {%0,%1,%2,%3};"              \
        : "+f"((c)[0]), "+f"((c)[1]), "+f"((c)[2]), "+f"((c)[3])             \
        : "r"((a)[0]), "r"((a)[1]), "r"((a)[2]), "r"((a)[3]),                \
          "r"((b)[0]), "r"((b)[1]))
#define MMA_F16(c, a, b)                                                     \
    asm volatile("mma.sync.aligned.m16n8k16.row.col.f32.f16.f16.f32 "        \
        "{%0,%1,%2,%3}, {%4,%5,%6,%7}, {%8,%9}, {%0,%1,%2,%3};"              \
        : "+f"((c)[0]), "+f"((c)[1]), "+f"((c)[2]), "+f"((c)[3])             \
        : "r"((a)[0]), "r"((a)[1]), "r"((a)[2]), "r"((a)[3]),                \
          "r"((b)[0]), "r"((b)[1]))

__device__ __forceinline__ uint32_t packh2(float a, float b) {
    __half2 h = __floats2half2_rn(a, b);
    return *(uint32_t*)&h;
}
__device__ __forceinline__ uint32_t packbf2(float a, float b) {
    __nv_bfloat16 x = __float2bfloat16(a), y = __float2bfloat16(b);
    return (uint32_t)*(unsigned short*)&x | ((uint32_t)*(unsigned short*)&y << 16);
}

// ---------------------------------------------------------------------------
// Global scratch
// ---------------------------------------------------------------------------
__device__ float g_bias[HH * (2 * SS - 1)];
__device__ __nv_bfloat16 g_ahi[BB * SS * DD];   // x splits, then ctx splits
__device__ __nv_bfloat16 g_alo[BB * SS * DD];
__device__ __nv_bfloat16 g_wthi[DD * DD];
__device__ __nv_bfloat16 g_wtlo[DD * DD];
__device__ __nv_bfloat16 g_qhi[BB * HH * SS * DK];
__device__ __nv_bfloat16 g_qlo[BB * HH * SS * DK];
__device__ __nv_bfloat16 g_khi[BB * HH * SS * DK];
__device__ __nv_bfloat16 g_klo[BB * HH * SS * DK];
__device__ __half        g_vh [BB * HH * SS * DK];

// ---------------------------------------------------------------------------
// Bias table (exact integer reduction of the T5 bucket function)
// ---------------------------------------------------------------------------
__global__ void bias_kernel(const float* __restrict__ rel_emb) {
    int idx = blockIdx.x * blockDim.x + threadIdx.x;
    const int TAB = 2 * SS - 1;
    if (idx >= HH * TAB) return;
    int h = idx / TAB, pos = idx % TAB;
    int n = -(pos - (SS - 1));
    int ret = 0;
    if (n < 0) { ret = 16; n = -n; }
    int v;
    if (n < 8) v = n;
    else {
        int j = (31 - __clz(n * n)) - 6;
        v = 8 + j;
        if (v > 15) v = 15;
    }
    g_bias[idx] = rel_emb[(ret + v) * HH + h];
}

// ---------------------------------------------------------------------------
// fp32 -> bf16 hi/lo split (x only)
// ---------------------------------------------------------------------------
__global__ void split_kernel(const float* __restrict__ src,
                             __nv_bfloat16* __restrict__ hi,
                             __nv_bfloat16* __restrict__ lo, int n4) {
    int i = blockIdx.x * blockDim.x + threadIdx.x;
    if (i >= n4) return;
    float4 v = ((const float4*)src)[i];
    __nv_bfloat16 h[4], l[4];
    float vv[4] = {v.x, v.y, v.z, v.w};
#pragma unroll
    for (int j = 0; j < 4; ++j) {
        h[j] = __float2bfloat16(vv[j]);
        l[j] = __float2bfloat16(vv[j] - __bfloat162float(h[j]));
    }
    *(uint2*)&hi[4 * i] = *(uint2*)h;
    *(uint2*)&lo[4 * i] = *(uint2*)l;
}

// ---------------------------------------------------------------------------
// Transpose+split: Wt[n][k] = split(W[k][n])
// ---------------------------------------------------------------------------
__global__ void splitT_kernel(const float* __restrict__ W,
                              __nv_bfloat16* __restrict__ hi,
                              __nv_bfloat16* __restrict__ lo) {
    __shared__ float t[32][33];
    const int tx = threadIdx.x, ty = threadIdx.y;
    const int bx = blockIdx.x, by = blockIdx.y;
#pragma unroll
    for (int j = 0; j < 32; j += 8)
        t[ty + j][tx] = W[(by * 32 + ty + j) * DD + bx * 32 + tx];
    __syncthreads();
#pragma unroll
    for (int j = 0; j < 32; j += 8) {
        float v = t[tx][ty + j];
        __nv_bfloat16 h = __float2bfloat16(v);
        __nv_bfloat16 l = __float2bfloat16(v - __bfloat162float(h));
        int o = (bx * 32 + ty + j) * DD + by * 32 + tx;
        hi[o] = h;
        lo[o] = l;
    }
}

// ---------------------------------------------------------------------------
// bf16-split mma.sync GEMM (4-stage cp.async, 1 sync/iter)
//   MODE 0: fp32 row-major out (o1)
//   MODE 1: bf16 hi/lo out scattered to [B,H,S,DK] (o1=hi, o2=lo)
//   MODE 2: fp16 out scattered to [B,H,S,DK] (o1)
// ---------------------------------------------------------------------------
#define ROWB   80
#define AT_B   (128 * ROWB)
#define STG_B  (2 * AT_B)
#define GEMM_SMEM (4 * STG_B)

template <int MODE>
__global__ __launch_bounds__(256, 2)
void tc_gemm(const __nv_bfloat16* __restrict__ Ahi,
             const __nv_bfloat16* __restrict__ Alo,
             const __nv_bfloat16* __restrict__ Bhi,
             const __nv_bfloat16* __restrict__ Blo,
             void* __restrict__ o1, void* __restrict__ o2) {
    extern __shared__ __align__(128) char smc[];
    const uint32_t sb = smem_u32(smc);
    const int tid = threadIdx.x;
    const int lane = tid & 31, wid = tid >> 5;
    const int m0 = blockIdx.y * 128, n0 = blockIdx.x * 128;

    const int lrow = tid >> 1;
    const int lsub = (tid & 1) * 32;

    const int wm = (wid & 3) * 32;
    const int wn = (wid >> 2) * 64;
    const uint32_t aoff = (uint32_t)(wm + (lane & 15)) * ROWB + (lane >> 4) * 16;
    const uint32_t boff = AT_B +
        (uint32_t)(wn + (lane & 7) + (lane >> 4) * 8) * ROWB + ((lane >> 3) & 1) * 16;

    float c[2][8][4];
#pragma unroll
    for (int i = 0; i < 2; ++i)
#pragma unroll
        for (int j = 0; j < 8; ++j)
#pragma unroll
            for (int q = 0; q < 4; ++q) c[i][j][q] = 0.0f;

    const int NIT = 96;

    auto issue = [&](int t) {
        const int p = t >> 5;
        const int kb = (t & 31) * 32;
        const __nv_bfloat16* Ap = (p == 1) ? Alo : Ahi;
        const __nv_bfloat16* Bp = (p == 2) ? Blo : Bhi;
        const uint32_t dstA = sb + (t & 3) * STG_B + lrow * ROWB + lsub;
        const uint32_t dstB = dstA + AT_B;
        const char* srcA = (const char*)(Ap + (size_t)(m0 + lrow) * DD + kb) + lsub;
        const char* srcB = (const char*)(Bp + (size_t)(n0 + lrow) * DD + kb) + lsub;
        CP_ASYNC16(dstA, srcA);
        CP_ASYNC16(dstA + 16, srcA + 16);
        CP_ASYNC16(dstB, srcB);
        CP_ASYNC16(dstB + 16, srcB + 16);
    };

    issue(0); CP_COMMIT();
    issue(1); CP_COMMIT();
    issue(2); CP_COMMIT();

    for (int t = 0; t < NIT; ++t) {
        CP_WAIT2();
        __syncthreads();
        if (t + 3 < NIT) issue(t + 3);
        CP_COMMIT();

        const uint32_t stg = sb + (t & 3) * STG_B;
#pragma unroll
        for (int s = 0; s < 2; ++s) {
            uint32_t ar[2][4], br[4][4];
#pragma unroll
            for (int mi = 0; mi < 2; ++mi)
                LDSM4(ar[mi], stg + aoff + mi * (16 * ROWB) + s * 32);
#pragma unroll
            for (int p = 0; p < 4; ++p)
                LDSM4(br[p], stg + boff + p * (16 * ROWB) + s * 32);
#pragma unroll
            for (int mi = 0; mi < 2; ++mi)
#pragma unroll
                for (int nj = 0; nj < 8; ++nj) {
                    uint32_t bf[2] = {br[nj >> 1][(nj & 1) * 2],
                                      br[nj >> 1][(nj & 1) * 2 + 1]};
                    MMA_BF16(c[mi][nj], ar[mi], bf);
                }
        }
    }

#pragma unroll
    for (int mi = 0; mi < 2; ++mi) {
#pragma unroll
        for (int nj = 0; nj < 8; ++nj) {
            const int col = n0 + wn + nj * 8 + (lane & 3) * 2;
            const int r = m0 + wm + mi * 16 + (lane >> 2);
            if (MODE == 0) {
                float* out = (float*)o1;
                *(float2*)&out[(size_t)r * DD + col] =
                    make_float2(c[mi][nj][0], c[mi][nj][1]);
                *(float2*)&out[(size_t)(r + 8) * DD + col] =
                    make_float2(c[mi][nj][2], c[mi][nj][3]);
            } else {
                const int h = col >> 6, d = col & 63;
#pragma unroll
                for (int half = 0; half < 2; ++half) {
                    const int rr = r + half * 8;
                    const int b = rr >> 10, s2 = rr & 1023;
                    const size_t idx =
                        ((size_t)((b << 4) + h) * 1024 + s2) * 64 + d;
                    float v0 = c[mi][nj][half * 2], v1 = c[mi][nj][half * 2 + 1];
                    if (MODE == 1) {
                        __nv_bfloat16 h0 = __float2bfloat16(v0);
                        __nv_bfloat16 h1 = __float2bfloat16(v1);
                        float l0 = v0 - __bfloat162float(h0);
                        float l1 = v1 - __bfloat162float(h1);
                        ((uint32_t*)o1)[idx >> 1] =
                            (uint32_t)*(unsigned short*)&h0 |
                            ((uint32_t)*(unsigned short*)&h1 << 16);
                        ((uint32_t*)o2)[idx >> 1] = packbf2(l0, l1);
                    } else {
                        ((uint32_t*)o1)[idx >> 1] = packh2(v0, v1);
                    }
                }
            }
        }
    }
}

// ---------------------------------------------------------------------------
// Tensor-core flash attention.
//   CTA: 128 q-rows x one (b,h). 8 warps, warp = 16 q-rows.
//   QK^T: bf16 3-product split.  P@V: single fp16 product.
//   K/V double-buffered (KT=64), one __syncthreads per k-tile.
//   Epilogue writes ctx bf16 hi/lo splits to g_ahi/g_alo [B,S,H*DK].
// ---------------------------------------------------------------------------
#define KT      64
#define RSB     144                    // smem row stride bytes (72 bf16)
#define Q_B     (128 * RSB)            // 18432 per Q tile
#define KV_T    (KT * RSB)             // 9216 per tile
#define KV_STG  (3 * KV_T)             // Khi, Klo, V
#define SM_KV   (2 * Q_B)              // K/V stages start
#define SM_BIAS (SM_KV + 2 * KV_STG)   // 92160
#define ATT_SMEM (SM_BIAS + 1152 * 4)  // 96768

__global__ __launch_bounds__(256, 2)
void attn_kernel() {
    extern __shared__ __align__(128) char smc[];
    const uint32_t sb = smem_u32(smc);
    float* bs = (float*)(smc + SM_BIAS);

    const int tid = threadIdx.x;
    const int lane = tid & 31, wid = tid >> 5;
    const int q0 = blockIdx.x * 128;
    const int h = blockIdx.y, b = blockIdx.z;
    const size_t hd = (size_t)(b * HH + h) * SS * DK;

    const int wm = wid * 16;
    const uint32_t aoff = (uint32_t)(wm + (lane & 15)) * RSB + (lane >> 4) * 16;
    const uint32_t boff = (uint32_t)((lane & 7) + (lane >> 4) * 8) * RSB +
                          ((lane >> 3) & 1) * 16;
    const uint32_t voff = (uint32_t)(lane & 15) * RSB + (lane >> 4) * 16;

    // ---- prologue loads: Q hi/lo, bias, KV stage 0 ----
    {
        const char* qh = (const char*)(g_qhi + hd + (size_t)q0 * DK);
        const char* ql = (const char*)(g_qlo + hd + (size_t)q0 * DK);
#pragma unroll
        for (int j = 0; j < 4; ++j) {
            int idx = tid + j * 256;               // 1024 chunks per tile
            int row = idx >> 3, ch = (idx & 7) * 16;
            CP_ASYNC16(sb + row * RSB + ch, qh + row * 128 + ch);
            CP_ASYNC16(sb + Q_B + row * RSB + ch, ql + row * 128 + ch);
        }
        for (int i = tid; i < 1151; i += 256)
            bs[i] = g_bias[h * (2 * SS - 1) + (896 - q0) + i];
    }
    auto issue_kv = [&](int kt) {
        const uint32_t stg = sb + SM_KV + (kt & 1) * KV_STG;
        const int k0 = kt * KT;
        const char* kh = (const char*)(g_khi + hd + (size_t)k0 * DK);
        const char* kl = (const char*)(g_klo + hd + (size_t)k0 * DK);
        const char* vv = (const char*)(g_vh + hd + (size_t)k0 * DK);
#pragma unroll
        for (int j = 0; j < 6; ++j) {
            int idx = tid + j * 256;               // 1536 chunks
            int tile = idx >> 9, rem = idx & 511;
            int row = rem >> 3, ch = (rem & 7) * 16;
            const char* src = (tile == 0 ? kh : (tile == 1 ? kl : vv));
            CP_ASYNC16(stg + tile * KV_T + row * RSB + ch, src + row * 128 + ch);
        }
    };
    issue_kv(0);
    CP_COMMIT();

    float o[8][4];
#pragma unroll
    for (int j = 0; j < 8; ++j)
#pragma unroll
        for (int e = 0; e < 4; ++e) o[j][e] = 0.0f;
    float m0r = -1e30f, m1r = -1e30f, l0 = 0.0f, l1 = 0.0f;

    for (int kt = 0; kt < SS / KT; ++kt) {
        CP_WAIT0();
        __syncthreads();
        if (kt + 1 < SS / KT) { issue_kv(kt + 1); CP_COMMIT(); }

        const uint32_t kbh = sb + SM_KV + (kt & 1) * KV_STG;
        const uint32_t kbl = kbh + KV_T;
        const uint32_t vbb = kbh + 2 * KV_T;
        const int k0 = kt * KT;

        // ---- S = Q K^T (3-product bf16 split) ----
        float s[8][4];
#pragma unroll
        for (int j = 0; j < 8; ++j)
#pragma unroll
            for (int e = 0; e < 4; ++e) s[j][e] = 0.0f;

#pragma unroll
        for (int pr = 0; pr < 3; ++pr) {
            const uint32_t ab = (pr == 1) ? (sb + Q_B) : sb;
            const uint32_t bb = (pr == 2) ? kbl : kbh;
#pragma unroll
            for (int ks = 0; ks < 4; ++ks) {
                uint32_t a[4];
                LDSM4(a, ab + aoff + ks * 32);
#pragma unroll
                for (int p = 0; p < 4; ++p) {
                    uint32_t bt[4];
                    LDSM4(bt, bb + boff + p * (16 * RSB) + ks * 32);
                    MMA_BF16(s[2 * p], a, bt);
                    MMA_BF16(s[2 * p + 1], a, bt + 2);
                }
            }
        }

        // ---- bias + online softmax ----
        const int qr0 = wm + (lane >> 2);
        const int cb0 = 127 + k0 + (lane & 3) * 2;
#pragma unroll
        for (int nj = 0; nj < 8; ++nj) {
            const int t0 = cb0 + nj * 8;
            s[nj][0] += bs[t0 - qr0];
            s[nj][1] += bs[t0 + 1 - qr0];
            s[nj][2] += bs[t0 - qr0 - 8];
            s[nj][3] += bs[t0 + 1 - qr0 - 8];
        }
        float mx0 = -1e30f, mx1 = -1e30f;
#pragma unroll
        for (int nj = 0; nj < 8; ++nj) {
            mx0 = fmaxf(mx0, fmaxf(s[nj][0], s[nj][1]));
            mx1 = fmaxf(mx1, fmaxf(s[nj][2], s[nj][3]));
        }
        mx0 = fmaxf(mx0, __shfl_xor_sync(0xffffffffu, mx0, 1));
        mx0 = fmaxf(mx0, __shfl_xor_sync(0xffffffffu, mx0, 2));
        mx1 = fmaxf(mx1, __shfl_xor_sync(0xffffffffu, mx1, 1));
        mx1 = fmaxf(mx1, __shfl_xor_sync(0xffffffffu, mx1, 2));
        const float mn0 = fmaxf(m0r, mx0), mn1 = fmaxf(m1r, mx1);
        const float al0 = __expf(m0r - mn0), al1 = __expf(m1r - mn1);
        m0r = mn0; m1r = mn1;
        float sum0 = 0.0f, sum1 = 0.0f;
#pragma unroll
        for (int nj = 0; nj < 8; ++nj) {
            s[nj][0] = __expf(s[nj][0] - mn0);
            s[nj][1] = __expf(s[nj][1] - mn0);
            s[nj][2] = __expf(s[nj][2] - mn1);
            s[nj][3] = __expf(s[nj][3] - mn1);
            sum0 += s[nj][0] + s[nj][1];
            sum1 += s[nj][2] + s[nj][3];
            o[nj][0] *= al0; o[nj][1] *= al0;
            o[nj][2] *= al1; o[nj][3] *= al1;
        }
        sum0 += __shfl_xor_sync(0xffffffffu, sum0, 1);
        sum0 += __shfl_xor_sync(0xffffffffu, sum0, 2);
        sum1 += __shfl_xor_sync(0xffffffffu, sum1, 1);
        sum1 += __shfl_xor_sync(0xffffffffu, sum1, 2);
        l0 = l0 * al0 + sum0;
        l1 = l1 * al1 + sum1;

        // ---- O += P V (fp16) ----
#pragma unroll
        for (int kc = 0; kc < 4; ++kc) {
            uint32_t ap[4];
            ap[0] = packh2(s[2 * kc][0], s[2 * kc][1]);
            ap[1] = packh2(s[2 * kc][2], s[2 * kc][3]);
            ap[2] = packh2(s[2 * kc + 1][0], s[2 * kc + 1][1]);
            ap[3] = packh2(s[2 * kc + 1][2], s[2 * kc + 1][3]);
#pragma unroll
            for (int nb = 0; nb < 4; ++nb) {
                uint32_t bt[4];
                LDSM4T(bt, vbb + voff + kc * (16 * RSB) + nb * 32);
                MMA_F16(o[2 * nb], ap, bt);
                MMA_F16(o[2 * nb + 1], ap, bt + 2);
            }
        }
    }

    // ---- epilogue: ctx -> bf16 hi/lo splits [B,S,H*DK] ----
    const float inv0 = 1.0f / l0, inv1 = 1.0f / l1;
    const int row0 = q0 + wm + (lane >> 2);
    const size_t base0 = ((size_t)(b * SS) + row0) * DD + h * 64;
    const size_t base1 = base0 + 8 * DD;
#pragma unroll
    for (int nj = 0; nj < 8; ++nj) {
        const int d = nj * 8 + (lane & 3) * 2;
        {
            float v0 = o[nj][0] * inv0, v1 = o[nj][1] * inv0;
            __nv_bfloat16 h0 = __float2bfloat16(v0);
            __nv_bfloat16 h1 = __float2bfloat16(v1);
            ((uint32_t*)g_ahi)[(base0 + d) >> 1] =
                (uint32_t)*(unsigned short*)&h0 |
                ((uint32_t)*(unsigned short*)&h1 << 16);
            ((uint32_t*)g_alo)[(base0 + d) >> 1] =
                packbf2(v0 - __bfloat162float(h0), v1 - __bfloat162float(h1));
        }
        {
            float v0 = o[nj][2] * inv1, v1 = o[nj][3] * inv1;
            __nv_bfloat16 h0 = __float2bfloat16(v0);
            __nv_bfloat16 h1 = __float2bfloat16(v1);
            ((uint32_t*)g_ahi)[(base1 + d) >> 1] =
                (uint32_t)*(unsigned short*)&h0 |
                ((uint32_t)*(unsigned short*)&h1 << 16);
            ((uint32_t*)g_alo)[(base1 + d) >> 1] =
                packbf2(v0 - __bfloat162float(h0), v1 - __bfloat162float(h1));
        }
    }
}

// ---------------------------------------------------------------------------
// Launch
// ---------------------------------------------------------------------------
extern "C" void kernel_launch(void* const* d_in, const int* in_sizes, int n_in,
                              void* d_out, int out_size) {
    const float* x   = (const float*)d_in[0];
    const float* Wq  = (const float*)d_in[1];
    const float* Wk  = (const float*)d_in[2];
    const float* Wv  = (const float*)d_in[3];
    const float* Wo  = (const float*)d_in[4];
    const float* rel = (const float*)d_in[5];
    float* out = (float*)d_out;

    __nv_bfloat16 *pah, *pal, *pwh, *pwl, *pqh, *pql, *pkh, *pkl;
    __half* pvh;
    cudaGetSymbolAddress((void**)&pah, g_ahi);
    cudaGetSymbolAddress((void**)&pal, g_alo);
    cudaGetSymbolAddress((void**)&pwh, g_wthi);
    cudaGetSymbolAddress((void**)&pwl, g_wtlo);
    cudaGetSymbolAddress((void**)&pqh, g_qhi);
    cudaGetSymbolAddress((void**)&pql, g_qlo);
    cudaGetSymbolAddress((void**)&pkh, g_khi);
    cudaGetSymbolAddress((void**)&pkl, g_klo);
    cudaGetSymbolAddress((void**)&pvh, g_vh);

    static bool attr_set = false;
    if (!attr_set) {
        cudaFuncSetAttribute(tc_gemm<0>, cudaFuncAttributeMaxDynamicSharedMemorySize, GEMM_SMEM);
        cudaFuncSetAttribute(tc_gemm<1>, cudaFuncAttributeMaxDynamicSharedMemorySize, GEMM_SMEM);
        cudaFuncSetAttribute(tc_gemm<2>, cudaFuncAttributeMaxDynamicSharedMemorySize, GEMM_SMEM);
        cudaFuncSetAttribute(attn_kernel, cudaFuncAttributeMaxDynamicSharedMemorySize, ATT_SMEM);
        attr_set = true;
    }

    bias_kernel<<<(HH * (2 * SS - 1) + 255) / 256, 256>>>(rel);

    const int n4 = BB * SS * DD / 4;
    split_kernel<<<(n4 + 255) / 256, 256>>>(x, pah, pal, n4);

    dim3 tg(32, 32), tb(32, 8);
    dim3 gg(DD / 128, (BB * SS) / 128);
    splitT_kernel<<<tg, tb>>>(Wq, pwh, pwl);
    tc_gemm<1><<<gg, 256, GEMM_SMEM>>>(pah, pal, pwh, pwl, pqh, pql);
    splitT_kernel<<<tg, tb>>>(Wk, pwh, pwl);
    tc_gemm<1><<<gg, 256, GEMM_SMEM>>>(pah, pal, pwh, pwl, pkh, pkl);
    splitT_kernel<<<tg, tb>>>(Wv, pwh, pwl);
    tc_gemm<2><<<gg, 256, GEMM_SMEM>>>(pah, pal, pwh, pwl, pvh, nullptr);

    dim3 ag(SS / 128, HH, BB);
    attn_kernel<<<ag, 256, ATT_SMEM>>>();

    splitT_kernel<<<tg, tb>>>(Wo, pwh, pwl);
    tc_gemm<0><<<gg, 256, GEMM_SMEM>>>(pah, pal, pwh, pwl, out, nullptr);
}

// round 5
// speedup vs baseline: 3.2009x; 1.2797x over previous
#include <cuda_runtime.h>
#include <cuda_bf16.h>
#include <cuda_fp16.h>
#include <math.h>
#include <stdint.h>

#define BB   8
#define SS   1024
#define DD   1024
#define HH   16
#define DK   64

__device__ __forceinline__ uint32_t smem_u32(const void* p) {
    uint32_t a;
    asm("{ .reg .u64 t; cvta.to.shared.u64 t, %1; cvt.u32.u64 %0, t; }"
        : "=r"(a) : "l"(p));
    return a;
}

#define CP_ASYNC16(dst, src) \
    asm volatile("cp.async.cg.shared.global [%0], [%1], 16;" :: "r"(dst), "l"(src))
#define CP_COMMIT() asm volatile("cp.async.commit_group;" ::: "memory")
#define CP_WAIT0()  asm volatile("cp.async.wait_group 0;" ::: "memory")
#define CP_WAIT1()  asm volatile("cp.async.wait_group 1;" ::: "memory")

#define LDSM4(r, a)                                                          \
    asm volatile("ldmatrix.sync.aligned.m8n8.x4.shared.b16 {%0,%1,%2,%3}, [%4];" \
        : "=r"((r)[0]), "=r"((r)[1]), "=r"((r)[2]), "=r"((r)[3]) : "r"(a))
#define LDSM4T(r, a)                                                         \
    asm volatile("ldmatrix.sync.aligned.m8n8.x4.trans.shared.b16 {%0,%1,%2,%3}, [%4];" \
        : "=r"((r)[0]), "=r"((r)[1]), "=r"((r)[2]), "=r"((r)[3]) : "r"(a))

#define MMA_BF16(c, a, b)                                                    \
    asm volatile("mma.sync.aligned.m16n8k16.row.col.f32.bf16.bf16.f32 "      \
        "{%0,%1,%2,%3}, {%4,%5,%6,%7}, {%8,%9}, {%0,%1,%2,%3};"              \
        : "+f"((c)[0]), "+f"((c)[1]), "+f"((c)[2]), "+f"((c)[3])             \
        : "r"((a)[0]), "r"((a)[1]), "r"((a)[2]), "r"((a)[3]),                \
          "r"((b)[0]), "r"((b)[1]))
#define MMA_F16(c, a, b)                                                     \
    asm volatile("mma.sync.aligned.m16n8k16.row.col.f32.f16.f16.f32 "        \
        "{%0,%1,%2,%3}, {%4,%5,%6,%7}, {%8,%9}, {%0,%1,%2,%3};"              \
        : "+f"((c)[0]), "+f"((c)[1]), "+f"((c)[2]), "+f"((c)[3])             \
        : "r"((a)[0]), "r"((a)[1]), "r"((a)[2]), "r"((a)[3]),                \
          "r"((b)[0]), "r"((b)[1]))

__device__ __forceinline__ uint32_t packh2(float a, float b) {
    __half2 h = __floats2half2_rn(a, b);
    return *(uint32_t*)&h;
}
__device__ __forceinline__ uint32_t packbf2(float a, float b) {
    __nv_bfloat16 x = __float2bfloat16(a), y = __float2bfloat16(b);
    return (uint32_t)*(unsigned short*)&x | ((uint32_t)*(unsigned short*)&y << 16);
}

// ---------------------------------------------------------------------------
// Global scratch
// ---------------------------------------------------------------------------
__device__ float g_bias[HH * (2 * SS - 1)];
__device__ __nv_bfloat16 g_ahi[BB * SS * DD];   // x splits, then ctx splits
__device__ __nv_bfloat16 g_alo[BB * SS * DD];
__device__ __nv_bfloat16 g_wthi[3 * DD * DD];   // concat [WqT;WkT;WvT] (or WoT)
__device__ __nv_bfloat16 g_wtlo[3 * DD * DD];
__device__ __nv_bfloat16 g_qhi[BB * HH * SS * DK];
__device__ __nv_bfloat16 g_qlo[BB * HH * SS * DK];
__device__ __nv_bfloat16 g_khi[BB * HH * SS * DK];
__device__ __nv_bfloat16 g_klo[BB * HH * SS * DK];
__device__ __half        g_vh [BB * HH * SS * DK];

// ---------------------------------------------------------------------------
// Bias table (exact integer reduction of the T5 bucket function)
// ---------------------------------------------------------------------------
__global__ void bias_kernel(const float* __restrict__ rel_emb) {
    int idx = blockIdx.x * blockDim.x + threadIdx.x;
    const int TAB = 2 * SS - 1;
    if (idx >= HH * TAB) return;
    int h = idx / TAB, pos = idx % TAB;
    int n = -(pos - (SS - 1));
    int ret = 0;
    if (n < 0) { ret = 16; n = -n; }
    int v;
    if (n < 8) v = n;
    else {
        int j = (31 - __clz(n * n)) - 6;
        v = 8 + j;
        if (v > 15) v = 15;
    }
    g_bias[idx] = rel_emb[(ret + v) * HH + h];
}

// ---------------------------------------------------------------------------
// fp32 -> bf16 hi/lo split (x)
// ---------------------------------------------------------------------------
__global__ void split_kernel(const float* __restrict__ src,
                             __nv_bfloat16* __restrict__ hi,
                             __nv_bfloat16* __restrict__ lo, int n4) {
    int i = blockIdx.x * blockDim.x + threadIdx.x;
    if (i >= n4) return;
    float4 v = ((const float4*)src)[i];
    __nv_bfloat16 h[4], l[4];
    float vv[4] = {v.x, v.y, v.z, v.w};
#pragma unroll
    for (int j = 0; j < 4; ++j) {
        h[j] = __float2bfloat16(vv[j]);
        l[j] = __float2bfloat16(vv[j] - __bfloat162float(h[j]));
    }
    *(uint2*)&hi[4 * i] = *(uint2*)h;
    *(uint2*)&lo[4 * i] = *(uint2*)l;
}

// ---------------------------------------------------------------------------
// Transpose+split with row offset: Wt[rowoff+n][k] = split(W[k][n])
// ---------------------------------------------------------------------------
__global__ void splitT_kernel(const float* __restrict__ W,
                              __nv_bfloat16* __restrict__ hi,
                              __nv_bfloat16* __restrict__ lo, int rowoff) {
    __shared__ float t[32][33];
    const int tx = threadIdx.x, ty = threadIdx.y;
    const int bx = blockIdx.x, by = blockIdx.y;
#pragma unroll
    for (int j = 0; j < 32; j += 8)
        t[ty + j][tx] = W[(by * 32 + ty + j) * DD + bx * 32 + tx];
    __syncthreads();
#pragma unroll
    for (int j = 0; j < 32; j += 8) {
        float v = t[tx][ty + j];
        __nv_bfloat16 h = __float2bfloat16(v);
        __nv_bfloat16 l = __float2bfloat16(v - __bfloat162float(h));
        size_t o = (size_t)(rowoff + bx * 32 + ty + j) * DD + by * 32 + tx;
        hi[o] = h;
        lo[o] = l;
    }
}

// ---------------------------------------------------------------------------
// bf16-split mma.sync GEMM, k-chunk=64, 3-stage cp.async ring, B-frag
// double buffering.  CTA 128x128, 8 warps (4x2), warp 32x64.
//   MODE 0: fp32 row-major out (oV arg unused)
//   MODE 3: fused QKV routing (N=3072): sect0->Q hi/lo, sect1->K hi/lo,
//           sect2->V fp16, scattered to [B,H,S,DK].
// ---------------------------------------------------------------------------
#define GRSB   144                     // smem row stride bytes (72 bf16)
#define AT_B   (128 * GRSB)            // 18432 per tile
#define STG_B  (2 * AT_B)              // 36864 per stage
#define GEMM_SMEM (3 * STG_B)          // 110592

template <int MODE>
__global__ __launch_bounds__(256, 2)
void tc_gemm(const __nv_bfloat16* __restrict__ Ahi,
             const __nv_bfloat16* __restrict__ Alo,
             const __nv_bfloat16* __restrict__ Bhi,
             const __nv_bfloat16* __restrict__ Blo,
             void* __restrict__ oQh, void* __restrict__ oQl,
             void* __restrict__ oKh, void* __restrict__ oKl,
             void* __restrict__ oV) {
    extern __shared__ __align__(128) char smc[];
    const uint32_t sb = smem_u32(smc);
    const int tid = threadIdx.x;
    const int lane = tid & 31, wid = tid >> 5;
    const int m0 = blockIdx.y * 128, n0 = blockIdx.x * 128;

    const int wm = (wid & 3) * 32;
    const int wn = (wid >> 2) * 64;
    const uint32_t aoff = (uint32_t)(wm + (lane & 15)) * GRSB + (lane >> 4) * 16;
    const uint32_t boff = AT_B +
        (uint32_t)(wn + (lane & 7) + (lane >> 4) * 8) * GRSB + ((lane >> 3) & 1) * 16;

    float c[2][8][4];
#pragma unroll
    for (int i = 0; i < 2; ++i)
#pragma unroll
        for (int j = 0; j < 8; ++j)
#pragma unroll
            for (int q = 0; q < 4; ++q) c[i][j][q] = 0.0f;

    const int NIT = 48;  // 3 products x 16 k64-chunks

    const int lrow = tid >> 1;              // unused placeholder removal
    (void)lrow;

    auto issue = [&](int t) {
        const int p = t >> 4;
        const int kb = (t & 15) * 64;
        const __nv_bfloat16* Ap = (p == 1) ? Alo : Ahi;
        const __nv_bfloat16* Bp = (p == 2) ? Blo : Bhi;
        const uint32_t stg = sb + (t % 3) * STG_B;
        const char* sa = (const char*)(Ap + (size_t)m0 * DD + kb);
        const char* sbp = (const char*)(Bp + (size_t)n0 * DD + kb);
#pragma unroll
        for (int j = 0; j < 4; ++j) {
            const int idx = tid + j * 256;        // 1024 chunks per tile
            const int row = idx >> 3, ch = (idx & 7) * 16;
            CP_ASYNC16(stg + row * GRSB + ch, sa + (size_t)row * (DD * 2) + ch);
            CP_ASYNC16(stg + AT_B + row * GRSB + ch,
                       sbp + (size_t)row * (DD * 2) + ch);
        }
    };

    issue(0); CP_COMMIT();
    issue(1); CP_COMMIT();

    for (int t = 0; t < NIT; ++t) {
        CP_WAIT1();
        __syncthreads();
        if (t + 2 < NIT) issue(t + 2);
        CP_COMMIT();

        const uint32_t stg = sb + (t % 3) * STG_B;
        uint32_t a[2][4], bfr[2][4][4];
        // prime B phase 0
#pragma unroll
        for (int p = 0; p < 4; ++p)
            LDSM4(bfr[0][p], stg + boff + p * (16 * GRSB));
#pragma unroll
        for (int s = 0; s < 4; ++s) {
            const int cur = s & 1;
#pragma unroll
            for (int mi = 0; mi < 2; ++mi)
                LDSM4(a[mi], stg + aoff + mi * (16 * GRSB) + s * 32);
            if (s < 3) {
#pragma unroll
                for (int p = 0; p < 4; ++p)
                    LDSM4(bfr[cur ^ 1][p],
                          stg + boff + p * (16 * GRSB) + (s + 1) * 32);
            }
#pragma unroll
            for (int mi = 0; mi < 2; ++mi)
#pragma unroll
                for (int nj = 0; nj < 8; ++nj) {
                    uint32_t bf2[2] = {bfr[cur][nj >> 1][(nj & 1) * 2],
                                       bfr[cur][nj >> 1][(nj & 1) * 2 + 1]};
                    MMA_BF16(c[mi][nj], a[mi], bf2);
                }
        }
    }

    // ---- epilogue ----
    const int sect = n0 >> 10;   // MODE 3: 0=Q, 1=K, 2=V
#pragma unroll
    for (int mi = 0; mi < 2; ++mi) {
#pragma unroll
        for (int nj = 0; nj < 8; ++nj) {
            const int col = n0 + wn + nj * 8 + (lane & 3) * 2;
            const int r = m0 + wm + mi * 16 + (lane >> 2);
            if (MODE == 0) {
                float* out = (float*)oQh;
                *(float2*)&out[(size_t)r * DD + col] =
                    make_float2(c[mi][nj][0], c[mi][nj][1]);
                *(float2*)&out[(size_t)(r + 8) * DD + col] =
                    make_float2(c[mi][nj][2], c[mi][nj][3]);
            } else {
                const int cw = col & 1023;
                const int h = cw >> 6, d = cw & 63;
#pragma unroll
                for (int half = 0; half < 2; ++half) {
                    const int rr = r + half * 8;
                    const int b = rr >> 10, s2 = rr & 1023;
                    const size_t idx =
                        ((size_t)((b << 4) + h) * 1024 + s2) * 64 + d;
                    float v0 = c[mi][nj][half * 2], v1 = c[mi][nj][half * 2 + 1];
                    if (sect == 2) {
                        ((uint32_t*)oV)[idx >> 1] = packh2(v0, v1);
                    } else {
                        void* oh = (sect == 0) ? oQh : oKh;
                        void* ol = (sect == 0) ? oQl : oKl;
                        __nv_bfloat16 h0 = __float2bfloat16(v0);
                        __nv_bfloat16 h1 = __float2bfloat16(v1);
                        ((uint32_t*)oh)[idx >> 1] =
                            (uint32_t)*(unsigned short*)&h0 |
                            ((uint32_t)*(unsigned short*)&h1 << 16);
                        ((uint32_t*)ol)[idx >> 1] = packbf2(
                            v0 - __bfloat162float(h0), v1 - __bfloat162float(h1));
                    }
                }
            }
        }
    }
}

// ---------------------------------------------------------------------------
// Tensor-core flash attention (unchanged from R4).
// ---------------------------------------------------------------------------
#define KT      64
#define RSB     144
#define Q_B     (128 * RSB)
#define KV_T    (KT * RSB)
#define KV_STG  (3 * KV_T)
#define SM_KV   (2 * Q_B)
#define SM_BIAS (SM_KV + 2 * KV_STG)
#define ATT_SMEM (SM_BIAS + 1152 * 4)

__global__ __launch_bounds__(256, 2)
void attn_kernel() {
    extern __shared__ __align__(128) char smc[];
    const uint32_t sb = smem_u32(smc);
    float* bs = (float*)(smc + SM_BIAS);

    const int tid = threadIdx.x;
    const int lane = tid & 31, wid = tid >> 5;
    const int q0 = blockIdx.x * 128;
    const int h = blockIdx.y, b = blockIdx.z;
    const size_t hd = (size_t)(b * HH + h) * SS * DK;

    const int wm = wid * 16;
    const uint32_t aoff = (uint32_t)(wm + (lane & 15)) * RSB + (lane >> 4) * 16;
    const uint32_t boff = (uint32_t)((lane & 7) + (lane >> 4) * 8) * RSB +
                          ((lane >> 3) & 1) * 16;
    const uint32_t voff = (uint32_t)(lane & 15) * RSB + (lane >> 4) * 16;

    {
        const char* qh = (const char*)(g_qhi + hd + (size_t)q0 * DK);
        const char* ql = (const char*)(g_qlo + hd + (size_t)q0 * DK);
#pragma unroll
        for (int j = 0; j < 4; ++j) {
            int idx = tid + j * 256;
            int row = idx >> 3, ch = (idx & 7) * 16;
            CP_ASYNC16(sb + row * RSB + ch, qh + row * 128 + ch);
            CP_ASYNC16(sb + Q_B + row * RSB + ch, ql + row * 128 + ch);
        }
        for (int i = tid; i < 1151; i += 256)
            bs[i] = g_bias[h * (2 * SS - 1) + (896 - q0) + i];
    }
    auto issue_kv = [&](int kt) {
        const uint32_t stg = sb + SM_KV + (kt & 1) * KV_STG;
        const int k0 = kt * KT;
        const char* kh = (const char*)(g_khi + hd + (size_t)k0 * DK);
        const char* kl = (const char*)(g_klo + hd + (size_t)k0 * DK);
        const char* vv = (const char*)(g_vh + hd + (size_t)k0 * DK);
#pragma unroll
        for (int j = 0; j < 6; ++j) {
            int idx = tid + j * 256;
            int tile = idx >> 9, rem = idx & 511;
            int row = rem >> 3, ch = (rem & 7) * 16;
            const char* src = (tile == 0 ? kh : (tile == 1 ? kl : vv));
            CP_ASYNC16(stg + tile * KV_T + row * RSB + ch, src + row * 128 + ch);
        }
    };
    issue_kv(0);
    CP_COMMIT();

    float o[8][4];
#pragma unroll
    for (int j = 0; j < 8; ++j)
#pragma unroll
        for (int e = 0; e < 4; ++e) o[j][e] = 0.0f;
    float m0r = -1e30f, m1r = -1e30f, l0 = 0.0f, l1 = 0.0f;

    for (int kt = 0; kt < SS / KT; ++kt) {
        CP_WAIT0();
        __syncthreads();
        if (kt + 1 < SS / KT) { issue_kv(kt + 1); CP_COMMIT(); }

        const uint32_t kbh = sb + SM_KV + (kt & 1) * KV_STG;
        const uint32_t kbl = kbh + KV_T;
        const uint32_t vbb = kbh + 2 * KV_T;
        const int k0 = kt * KT;

        float s[8][4];
#pragma unroll
        for (int j = 0; j < 8; ++j)
#pragma unroll
            for (int e = 0; e < 4; ++e) s[j][e] = 0.0f;

#pragma unroll
        for (int pr = 0; pr < 3; ++pr) {
            const uint32_t ab = (pr == 1) ? (sb + Q_B) : sb;
            const uint32_t bb = (pr == 2) ? kbl : kbh;
#pragma unroll
            for (int ks = 0; ks < 4; ++ks) {
                uint32_t a[4];
                LDSM4(a, ab + aoff + ks * 32);
#pragma unroll
                for (int p = 0; p < 4; ++p) {
                    uint32_t bt[4];
                    LDSM4(bt, bb + boff + p * (16 * RSB) + ks * 32);
                    MMA_BF16(s[2 * p], a, bt);
                    MMA_BF16(s[2 * p + 1], a, bt + 2);
                }
            }
        }

        const int qr0 = wm + (lane >> 2);
        const int cb0 = 127 + k0 + (lane & 3) * 2;
#pragma unroll
        for (int nj = 0; nj < 8; ++nj) {
            const int t0 = cb0 + nj * 8;
            s[nj][0] += bs[t0 - qr0];
            s[nj][1] += bs[t0 + 1 - qr0];
            s[nj][2] += bs[t0 - qr0 - 8];
            s[nj][3] += bs[t0 + 1 - qr0 - 8];
        }
        float mx0 = -1e30f, mx1 = -1e30f;
#pragma unroll
        for (int nj = 0; nj < 8; ++nj) {
            mx0 = fmaxf(mx0, fmaxf(s[nj][0], s[nj][1]));
            mx1 = fmaxf(mx1, fmaxf(s[nj][2], s[nj][3]));
        }
        mx0 = fmaxf(mx0, __shfl_xor_sync(0xffffffffu, mx0, 1));
        mx0 = fmaxf(mx0, __shfl_xor_sync(0xffffffffu, mx0, 2));
        mx1 = fmaxf(mx1, __shfl_xor_sync(0xffffffffu, mx1, 1));
        mx1 = fmaxf(mx1, __shfl_xor_sync(0xffffffffu, mx1, 2));
        const float mn0 = fmaxf(m0r, mx0), mn1 = fmaxf(m1r, mx1);
        const float al0 = __expf(m0r - mn0), al1 = __expf(m1r - mn1);
        m0r = mn0; m1r = mn1;
        float sum0 = 0.0f, sum1 = 0.0f;
#pragma unroll
        for (int nj = 0; nj < 8; ++nj) {
            s[nj][0] = __expf(s[nj][0] - mn0);
            s[nj][1] = __expf(s[nj][1] - mn0);
            s[nj][2] = __expf(s[nj][2] - mn1);
            s[nj][3] = __expf(s[nj][3] - mn1);
            sum0 += s[nj][0] + s[nj][1];
            sum1 += s[nj][2] + s[nj][3];
            o[nj][0] *= al0; o[nj][1] *= al0;
            o[nj][2] *= al1; o[nj][3] *= al1;
        }
        sum0 += __shfl_xor_sync(0xffffffffu, sum0, 1);
        sum0 += __shfl_xor_sync(0xffffffffu, sum0, 2);
        sum1 += __shfl_xor_sync(0xffffffffu, sum1, 1);
        sum1 += __shfl_xor_sync(0xffffffffu, sum1, 2);
        l0 = l0 * al0 + sum0;
        l1 = l1 * al1 + sum1;

#pragma unroll
        for (int kc = 0; kc < 4; ++kc) {
            uint32_t ap[4];
            ap[0] = packh2(s[2 * kc][0], s[2 * kc][1]);
            ap[1] = packh2(s[2 * kc][2], s[2 * kc][3]);
            ap[2] = packh2(s[2 * kc + 1][0], s[2 * kc + 1][1]);
            ap[3] = packh2(s[2 * kc + 1][2], s[2 * kc + 1][3]);
#pragma unroll
            for (int nb = 0; nb < 4; ++nb) {
                uint32_t bt[4];
                LDSM4T(bt, vbb + voff + kc * (16 * RSB) + nb * 32);
                MMA_F16(o[2 * nb], ap, bt);
                MMA_F16(o[2 * nb + 1], ap, bt + 2);
            }
        }
    }

    const float inv0 = 1.0f / l0, inv1 = 1.0f / l1;
    const int row0 = q0 + wm + (lane >> 2);
    const size_t base0 = ((size_t)(b * SS) + row0) * DD + h * 64;
    const size_t base1 = base0 + 8 * DD;
#pragma unroll
    for (int nj = 0; nj < 8; ++nj) {
        const int d = nj * 8 + (lane & 3) * 2;
        {
            float v0 = o[nj][0] * inv0, v1 = o[nj][1] * inv0;
            __nv_bfloat16 h0 = __float2bfloat16(v0);
            __nv_bfloat16 h1 = __float2bfloat16(v1);
            ((uint32_t*)g_ahi)[(base0 + d) >> 1] =
                (uint32_t)*(unsigned short*)&h0 |
                ((uint32_t)*(unsigned short*)&h1 << 16);
            ((uint32_t*)g_alo)[(base0 + d) >> 1] =
                packbf2(v0 - __bfloat162float(h0), v1 - __bfloat162float(h1));
        }
        {
            float v0 = o[nj][2] * inv1, v1 = o[nj][3] * inv1;
            __nv_bfloat16 h0 = __float2bfloat16(v0);
            __nv_bfloat16 h1 = __float2bfloat16(v1);
            ((uint32_t*)g_ahi)[(base1 + d) >> 1] =
                (uint32_t)*(unsigned short*)&h0 |
                ((uint32_t)*(unsigned short*)&h1 << 16);
            ((uint32_t*)g_alo)[(base1 + d) >> 1] =
                packbf2(v0 - __bfloat162float(h0), v1 - __bfloat162float(h1));
        }
    }
}

// ---------------------------------------------------------------------------
// Launch
// ---------------------------------------------------------------------------
extern "C" void kernel_launch(void* const* d_in, const int* in_sizes, int n_in,
                              void* d_out, int out_size) {
    const float* x   = (const float*)d_in[0];
    const float* Wq  = (const float*)d_in[1];
    const float* Wk  = (const float*)d_in[2];
    const float* Wv  = (const float*)d_in[3];
    const float* Wo  = (const float*)d_in[4];
    const float* rel = (const float*)d_in[5];
    float* out = (float*)d_out;

    __nv_bfloat16 *pah, *pal, *pwh, *pwl, *pqh, *pql, *pkh, *pkl;
    __half* pvh;
    cudaGetSymbolAddress((void**)&pah, g_ahi);
    cudaGetSymbolAddress((void**)&pal, g_alo);
    cudaGetSymbolAddress((void**)&pwh, g_wthi);
    cudaGetSymbolAddress((void**)&pwl, g_wtlo);
    cudaGetSymbolAddress((void**)&pqh, g_qhi);
    cudaGetSymbolAddress((void**)&pql, g_qlo);
    cudaGetSymbolAddress((void**)&pkh, g_khi);
    cudaGetSymbolAddress((void**)&pkl, g_klo);
    cudaGetSymbolAddress((void**)&pvh, g_vh);

    static bool attr_set = false;
    if (!attr_set) {
        cudaFuncSetAttribute(tc_gemm<0>, cudaFuncAttributeMaxDynamicSharedMemorySize, GEMM_SMEM);
        cudaFuncSetAttribute(tc_gemm<3>, cudaFuncAttributeMaxDynamicSharedMemorySize, GEMM_SMEM);
        cudaFuncSetAttribute(attn_kernel, cudaFuncAttributeMaxDynamicSharedMemorySize, ATT_SMEM);
        attr_set = true;
    }

    bias_kernel<<<(HH * (2 * SS - 1) + 255) / 256, 256>>>(rel);

    const int n4 = BB * SS * DD / 4;
    split_kernel<<<(n4 + 255) / 256, 256>>>(x, pah, pal, n4);

    dim3 tg(32, 32), tb(32, 8);
    splitT_kernel<<<tg, tb>>>(Wq, pwh, pwl, 0);
    splitT_kernel<<<tg, tb>>>(Wk, pwh, pwl, 1024);
    splitT_kernel<<<tg, tb>>>(Wv, pwh, pwl, 2048);

    // fused QKV: N = 3072
    dim3 gq(3 * DD / 128, (BB * SS) / 128);   // (24, 64)
    tc_gemm<3><<<gq, 256, GEMM_SMEM>>>(pah, pal, pwh, pwl,
                                       pqh, pql, pkh, pkl, pvh);

    dim3 ag(SS / 128, HH, BB);
    attn_kernel<<<ag, 256, ATT_SMEM>>>();

    splitT_kernel<<<tg, tb>>>(Wo, pwh, pwl, 0);
    dim3 go(DD / 128, (BB * SS) / 128);       // (8, 64)
    tc_gemm<0><<<go, 256, GEMM_SMEM>>>(pah, pal, pwh, pwl,
                                       out, nullptr, nullptr, nullptr, nullptr);
}

// round 8
// speedup vs baseline: 3.8480x; 1.2022x over previous
#include <cuda_runtime.h>
#include <cuda_bf16.h>
#include <cuda_fp16.h>
#include <math.h>
#include <stdint.h>

#define BB   8
#define SS   1024
#define DD   1024
#define HH   16
#define DK   64

__device__ __forceinline__ uint32_t smem_u32(const void* p) {
    uint32_t a;
    asm("{ .reg .u64 t; cvta.to.shared.u64 t, %1; cvt.u32.u64 %0, t; }"
        : "=r"(a) : "l"(p));
    return a;
}

#define CP_ASYNC16(dst, src) \
    asm volatile("cp.async.cg.shared.global [%0], [%1], 16;" :: "r"(dst), "l"(src))
#define CP_COMMIT() asm volatile("cp.async.commit_group;" ::: "memory")
#define CP_WAIT0()  asm volatile("cp.async.wait_group 0;" ::: "memory")
#define CP_WAIT1()  asm volatile("cp.async.wait_group 1;" ::: "memory")

#define LDSM4(r, a)                                                          \
    asm volatile("ldmatrix.sync.aligned.m8n8.x4.shared.b16 {%0,%1,%2,%3}, [%4];" \
        : "=r"((r)[0]), "=r"((r)[1]), "=r"((r)[2]), "=r"((r)[3]) : "r"(a))
#define LDSM4T(r, a)                                                         \
    asm volatile("ldmatrix.sync.aligned.m8n8.x4.trans.shared.b16 {%0,%1,%2,%3}, [%4];" \
        : "=r"((r)[0]), "=r"((r)[1]), "=r"((r)[2]), "=r"((r)[3]) : "r"(a))

#define MMA_BF16(c, a, b)                                                    \
    asm volatile("mma.sync.aligned.m16n8k16.row.col.f32.bf16.bf16.f32 "      \
        "{%0,%1,%2,%3}, {%4,%5,%6,%7}, {%8,%9}, {%0,%1,%2,%3};"              \
        : "+f"((c)[0]), "+f"((c)[1]), "+f"((c)[2]), "+f"((c)[3])             \
        : "r"((a)[0]), "r"((a)[1]), "r"((a)[2]), "r"((a)[3]),                \
          "r"((b)[0]), "r"((b)[1]))
#define MMA_F16(c, a, b)                                                     \
    asm volatile("mma.sync.aligned.m16n8k16.row.col.f32.f16.f16.f32 "        \
        "{%0,%1,%2,%3}, {%4,%5,%6,%7}, {%8,%9}, {%0,%1,%2,%3};"              \
        : "+f"((c)[0]), "+f"((c)[1]), "+f"((c)[2]), "+f"((c)[3])             \
        : "r"((a)[0]), "r"((a)[1]), "r"((a)[2]), "r"((a)[3]),                \
          "r"((b)[0]), "r"((b)[1]))

__device__ __forceinline__ uint32_t packh2(float a, float b) {
    __half2 h = __floats2half2_rn(a, b);
    return *(uint32_t*)&h;
}
__device__ __forceinline__ uint32_t packbf2(float a, float b) {
    __nv_bfloat16 x = __float2bfloat16(a), y = __float2bfloat16(b);
    return (uint32_t)*(unsigned short*)&x | ((uint32_t)*(unsigned short*)&y << 16);
}

// ---------------------------------------------------------------------------
// Global scratch
// ---------------------------------------------------------------------------
__device__ float g_bias[HH * (2 * SS - 1)];
__device__ __nv_bfloat16 g_ahi[BB * SS * DD];   // x splits, then ctx splits
__device__ __nv_bfloat16 g_alo[BB * SS * DD];
__device__ __nv_bfloat16 g_wthi[4 * DD * DD];   // [WqT;WkT;WvT;WoT]
__device__ __nv_bfloat16 g_wtlo[4 * DD * DD];
__device__ __nv_bfloat16 g_qhi[BB * HH * SS * DK];
__device__ __nv_bfloat16 g_qlo[BB * HH * SS * DK];
__device__ __nv_bfloat16 g_khi[BB * HH * SS * DK];
__device__ __nv_bfloat16 g_klo[BB * HH * SS * DK];
__device__ __half        g_vh [BB * HH * SS * DK];

// ---------------------------------------------------------------------------
// Bias table (exact integer reduction of the T5 bucket function)
// ---------------------------------------------------------------------------
__global__ void bias_kernel(const float* __restrict__ rel_emb) {
    int idx = blockIdx.x * blockDim.x + threadIdx.x;
    const int TAB = 2 * SS - 1;
    if (idx >= HH * TAB) return;
    int h = idx / TAB, pos = idx % TAB;
    int n = -(pos - (SS - 1));
    int ret = 0;
    if (n < 0) { ret = 16; n = -n; }
    int v;
    if (n < 8) v = n;
    else {
        int j = (31 - __clz(n * n)) - 6;
        v = 8 + j;
        if (v > 15) v = 15;
    }
    g_bias[idx] = rel_emb[(ret + v) * HH + h];
}

// ---------------------------------------------------------------------------
// fp32 -> bf16 hi/lo split (x)
// ---------------------------------------------------------------------------
__global__ void split_kernel(const float* __restrict__ src,
                             __nv_bfloat16* __restrict__ hi,
                             __nv_bfloat16* __restrict__ lo, int n4) {
    int i = blockIdx.x * blockDim.x + threadIdx.x;
    if (i >= n4) return;
    float4 v = ((const float4*)src)[i];
    __nv_bfloat16 h[4], l[4];
    float vv[4] = {v.x, v.y, v.z, v.w};
#pragma unroll
    for (int j = 0; j < 4; ++j) {
        h[j] = __float2bfloat16(vv[j]);
        l[j] = __float2bfloat16(vv[j] - __bfloat162float(h[j]));
    }
    *(uint2*)&hi[4 * i] = *(uint2*)h;
    *(uint2*)&lo[4 * i] = *(uint2*)l;
}

// ---------------------------------------------------------------------------
// Fused transpose+split of all 4 weights (z selects the weight)
// ---------------------------------------------------------------------------
__global__ void splitT4_kernel(const float* __restrict__ W0,
                               const float* __restrict__ W1,
                               const float* __restrict__ W2,
                               const float* __restrict__ W3,
                               __nv_bfloat16* __restrict__ hi,
                               __nv_bfloat16* __restrict__ lo) {
    __shared__ float t[32][33];
    const int tx = threadIdx.x, ty = threadIdx.y;
    const int bx = blockIdx.x, by = blockIdx.y, bz = blockIdx.z;
    const float* W = (bz == 0) ? W0 : (bz == 1) ? W1 : (bz == 2) ? W2 : W3;
#pragma unroll
    for (int j = 0; j < 32; j += 8)
        t[ty + j][tx] = W[(by * 32 + ty + j) * DD + bx * 32 + tx];
    __syncthreads();
    const size_t zoff = (size_t)bz * DD * DD;
#pragma unroll
    for (int j = 0; j < 32; j += 8) {
        float v = t[tx][ty + j];
        __nv_bfloat16 h = __float2bfloat16(v);
        __nv_bfloat16 l = __float2bfloat16(v - __bfloat162float(h));
        size_t o = zoff + (size_t)(bx * 32 + ty + j) * DD + by * 32 + tx;
        hi[o] = h;
        lo[o] = l;
    }
}

// ---------------------------------------------------------------------------
// bf16-split mma.sync GEMM, fused-product mainloop.
//   Stage = 4 tiles (Ahi, Alo, Bhi, Blo) of one k32 chunk, unpadded 64B rows
//   with XOR chunk swizzle: phys16Bchunk = c ^ ((row>>1)&3) -> 16B-aligned,
//   ldmatrix/cp.async conflict-free.  All 3 split-products per chunk with
//   frag reuse (96 MMA / 24 ldsm per barrier).  CTA 128x128, 8 warps (4x2),
//   3-stage cp.async ring, 2 CTA/SM.
//   MODE 0: fp32 row-major out.  MODE 3: fused QKV routing.
// ---------------------------------------------------------------------------
#define T_B    8192                    // 128 rows x 64B
#define STG_B  (4 * T_B)               // 32768
#define GEMM_SMEM (3 * STG_B)          // 98304

template <int MODE>
__global__ __launch_bounds__(256, 2)
void tc_gemm(const __nv_bfloat16* __restrict__ Ahi,
             const __nv_bfloat16* __restrict__ Alo,
             const __nv_bfloat16* __restrict__ Bhi,
             const __nv_bfloat16* __restrict__ Blo,
             void* __restrict__ oQh, void* __restrict__ oQl,
             void* __restrict__ oKh, void* __restrict__ oKl,
             void* __restrict__ oV) {
    extern __shared__ __align__(128) char smc[];
    const uint32_t sb = smem_u32(smc);
    const int tid = threadIdx.x;
    const int lane = tid & 31, wid = tid >> 5;
    const int m0 = blockIdx.y * 128, n0 = blockIdx.x * 128;

    const int wm = (wid & 3) * 32;
    const int wn = (wid >> 2) * 64;

    // ldmatrix lane geometry (swizzled chunk computed per phase)
    const int arow = wm + (lane & 15);
    const uint32_t abase = (uint32_t)arow * 64;
    const int aswz = (arow >> 1) & 3;
    const int ahb = lane >> 4;                    // logical chunk low bit
    const int brow = wn + (lane & 7) + (lane >> 4) * 8;
    const uint32_t bbase = (uint32_t)brow * 64;
    const int bswz = (brow >> 1) & 3;
    const int bhb = (lane >> 3) & 1;

    float c[2][8][4];
#pragma unroll
    for (int i = 0; i < 2; ++i)
#pragma unroll
        for (int j = 0; j < 8; ++j)
#pragma unroll
            for (int q = 0; q < 4; ++q) c[i][j][q] = 0.0f;

    const int NIT = 32;   // k32 chunks over K=1024

    auto issue = [&](int t) {
        const int kb = t * 32;
        const uint32_t stg = sb + (t % 3) * STG_B;
        const char* s0 = (const char*)(Ahi + (size_t)m0 * DD + kb);
        const char* s1 = (const char*)(Alo + (size_t)m0 * DD + kb);
        const char* s2 = (const char*)(Bhi + (size_t)n0 * DD + kb);
        const char* s3 = (const char*)(Blo + (size_t)n0 * DD + kb);
#pragma unroll
        for (int j = 0; j < 8; ++j) {
            const int idx = tid + j * 256;        // 2048 = 4 tiles x 512 chunks
            const int tile = idx >> 9, rem = idx & 511;
            const int row = rem >> 2, ch = rem & 3;
            const int phys = ch ^ ((row >> 1) & 3);
            const char* src =
                ((tile == 0) ? s0 : (tile == 1) ? s1 : (tile == 2) ? s2 : s3) +
                (size_t)row * 2048 + ch * 16;
            CP_ASYNC16(stg + tile * T_B + row * 64 + phys * 16, src);
        }
    };

    issue(0); CP_COMMIT();
    issue(1); CP_COMMIT();

    for (int t = 0; t < NIT; ++t) {
        CP_WAIT1();
        __syncthreads();
        if (t + 2 < NIT) issue(t + 2);
        CP_COMMIT();

        const uint32_t stg = sb + (t % 3) * STG_B;
#pragma unroll
        for (int s = 0; s < 2; ++s) {           // k16 phases of the k32 chunk
            const uint32_t ac = (uint32_t)(((s * 2 + ahb) ^ aswz) * 16);
            const uint32_t bc = (uint32_t)(((s * 2 + bhb) ^ bswz) * 16);
            uint32_t ah[2][4], al[2][4], bf[4][4];
#pragma unroll
            for (int mi = 0; mi < 2; ++mi) {
                LDSM4(ah[mi], stg + abase + mi * 1024 + ac);
                LDSM4(al[mi], stg + T_B + abase + mi * 1024 + ac);
            }
            // Bhi frags
#pragma unroll
            for (int p = 0; p < 4; ++p)
                LDSM4(bf[p], stg + 2 * T_B + bbase + p * 1024 + bc);
            // hh + lh products share Bhi
#pragma unroll
            for (int mi = 0; mi < 2; ++mi)
#pragma unroll
                for (int nj = 0; nj < 8; ++nj) {
                    uint32_t b2[2] = {bf[nj >> 1][(nj & 1) * 2],
                                      bf[nj >> 1][(nj & 1) * 2 + 1]};
                    MMA_BF16(c[mi][nj], ah[mi], b2);
                    MMA_BF16(c[mi][nj], al[mi], b2);
                }
            // Blo frags (reuse registers)
#pragma unroll
            for (int p = 0; p < 4; ++p)
                LDSM4(bf[p], stg + 3 * T_B + bbase + p * 1024 + bc);
#pragma unroll
            for (int mi = 0; mi < 2; ++mi)
#pragma unroll
                for (int nj = 0; nj < 8; ++nj) {
                    uint32_t b2[2] = {bf[nj >> 1][(nj & 1) * 2],
                                      bf[nj >> 1][(nj & 1) * 2 + 1]};
                    MMA_BF16(c[mi][nj], ah[mi], b2);
                }
        }
    }

    // ---- epilogue ----
    const int sect = n0 >> 10;
#pragma unroll
    for (int mi = 0; mi < 2; ++mi) {
#pragma unroll
        for (int nj = 0; nj < 8; ++nj) {
            const int col = n0 + wn + nj * 8 + (lane & 3) * 2;
            const int r = m0 + wm + mi * 16 + (lane >> 2);
            if (MODE == 0) {
                float* out = (float*)oQh;
                *(float2*)&out[(size_t)r * DD + col] =
                    make_float2(c[mi][nj][0], c[mi][nj][1]);
                *(float2*)&out[(size_t)(r + 8) * DD + col] =
                    make_float2(c[mi][nj][2], c[mi][nj][3]);
            } else {
                const int cw = col & 1023;
                const int h = cw >> 6, d = cw & 63;
#pragma unroll
                for (int half = 0; half < 2; ++half) {
                    const int rr = r + half * 8;
                    const int b = rr >> 10, s2 = rr & 1023;
                    const size_t idx =
                        ((size_t)((b << 4) + h) * 1024 + s2) * 64 + d;
                    float v0 = c[mi][nj][half * 2], v1 = c[mi][nj][half * 2 + 1];
                    if (sect == 2) {
                        ((uint32_t*)oV)[idx >> 1] = packh2(v0, v1);
                    } else {
                        void* oh = (sect == 0) ? oQh : oKh;
                        void* ol = (sect == 0) ? oQl : oKl;
                        __nv_bfloat16 h0 = __float2bfloat16(v0);
                        __nv_bfloat16 h1 = __float2bfloat16(v1);
                        ((uint32_t*)oh)[idx >> 1] =
                            (uint32_t)*(unsigned short*)&h0 |
                            ((uint32_t)*(unsigned short*)&h1 << 16);
                        ((uint32_t*)ol)[idx >> 1] = packbf2(
                            v0 - __bfloat162float(h0), v1 - __bfloat162float(h1));
                    }
                }
            }
        }
    }
}

// ---------------------------------------------------------------------------
// Tensor-core flash attention (QK frag-reuse; 144B rows, 16B-aligned).
// ---------------------------------------------------------------------------
#define KT      64
#define RSB     144
#define Q_B     (128 * RSB)
#define KV_T    (KT * RSB)
#define KV_STG  (3 * KV_T)
#define SM_KV   (2 * Q_B)
#define SM_BIAS (SM_KV + 2 * KV_STG)
#define ATT_SMEM (SM_BIAS + 1152 * 4)

__global__ __launch_bounds__(256, 2)
void attn_kernel() {
    extern __shared__ __align__(128) char smc[];
    const uint32_t sb = smem_u32(smc);
    float* bs = (float*)(smc + SM_BIAS);

    const int tid = threadIdx.x;
    const int lane = tid & 31, wid = tid >> 5;
    const int q0 = blockIdx.x * 128;
    const int h = blockIdx.y, b = blockIdx.z;
    const size_t hd = (size_t)(b * HH + h) * SS * DK;

    const int wm = wid * 16;
    const uint32_t aoff = (uint32_t)(wm + (lane & 15)) * RSB + (lane >> 4) * 16;
    const uint32_t boff = (uint32_t)((lane & 7) + (lane >> 4) * 8) * RSB +
                          ((lane >> 3) & 1) * 16;
    const uint32_t voff = (uint32_t)(lane & 15) * RSB + (lane >> 4) * 16;

    {
        const char* qh = (const char*)(g_qhi + hd + (size_t)q0 * DK);
        const char* ql = (const char*)(g_qlo + hd + (size_t)q0 * DK);
#pragma unroll
        for (int j = 0; j < 4; ++j) {
            int idx = tid + j * 256;
            int row = idx >> 3, ch = (idx & 7) * 16;
            CP_ASYNC16(sb + row * RSB + ch, qh + row * 128 + ch);
            CP_ASYNC16(sb + Q_B + row * RSB + ch, ql + row * 128 + ch);
        }
        for (int i = tid; i < 1151; i += 256)
            bs[i] = g_bias[h * (2 * SS - 1) + (896 - q0) + i];
    }
    auto issue_kv = [&](int kt) {
        const uint32_t stg = sb + SM_KV + (kt & 1) * KV_STG;
        const int k0 = kt * KT;
        const char* kh = (const char*)(g_khi + hd + (size_t)k0 * DK);
        const char* kl = (const char*)(g_klo + hd + (size_t)k0 * DK);
        const char* vv = (const char*)(g_vh + hd + (size_t)k0 * DK);
#pragma unroll
        for (int j = 0; j < 6; ++j) {
            int idx = tid + j * 256;
            int tile = idx >> 9, rem = idx & 511;
            int row = rem >> 3, ch = (rem & 7) * 16;
            const char* src = (tile == 0 ? kh : (tile == 1 ? kl : vv));
            CP_ASYNC16(stg + tile * KV_T + row * RSB + ch, src + row * 128 + ch);
        }
    };
    issue_kv(0);
    CP_COMMIT();

    float o[8][4];
#pragma unroll
    for (int j = 0; j < 8; ++j)
#pragma unroll
        for (int e = 0; e < 4; ++e) o[j][e] = 0.0f;
    float m0r = -1e30f, m1r = -1e30f, l0 = 0.0f, l1 = 0.0f;

    for (int kt = 0; kt < SS / KT; ++kt) {
        CP_WAIT0();
        __syncthreads();
        if (kt + 1 < SS / KT) { issue_kv(kt + 1); CP_COMMIT(); }

        const uint32_t kbh = sb + SM_KV + (kt & 1) * KV_STG;
        const uint32_t kbl = kbh + KV_T;
        const uint32_t vbb = kbh + 2 * KV_T;
        const int k0 = kt * KT;

        float s[8][4];
#pragma unroll
        for (int j = 0; j < 8; ++j)
#pragma unroll
            for (int e = 0; e < 4; ++e) s[j][e] = 0.0f;

        // ---- S = Q K^T, fused 3-product with frag reuse ----
#pragma unroll
        for (int ks = 0; ks < 4; ++ks) {
            uint32_t ah[4], al[4];
            LDSM4(ah, sb + aoff + ks * 32);
            LDSM4(al, sb + Q_B + aoff + ks * 32);
#pragma unroll
            for (int p = 0; p < 4; ++p) {
                uint32_t bh[4], bl[4];
                LDSM4(bh, kbh + boff + p * (16 * RSB) + ks * 32);
                LDSM4(bl, kbl + boff + p * (16 * RSB) + ks * 32);
                MMA_BF16(s[2 * p], ah, bh);
                MMA_BF16(s[2 * p + 1], ah, bh + 2);
                MMA_BF16(s[2 * p], al, bh);
                MMA_BF16(s[2 * p + 1], al, bh + 2);
                MMA_BF16(s[2 * p], ah, bl);
                MMA_BF16(s[2 * p + 1], ah, bl + 2);
            }
        }

        const int qr0 = wm + (lane >> 2);
        const int cb0 = 127 + k0 + (lane & 3) * 2;
#pragma unroll
        for (int nj = 0; nj < 8; ++nj) {
            const int t0 = cb0 + nj * 8;
            s[nj][0] += bs[t0 - qr0];
            s[nj][1] += bs[t0 + 1 - qr0];
            s[nj][2] += bs[t0 - qr0 - 8];
            s[nj][3] += bs[t0 + 1 - qr0 - 8];
        }
        float mx0 = -1e30f, mx1 = -1e30f;
#pragma unroll
        for (int nj = 0; nj < 8; ++nj) {
            mx0 = fmaxf(mx0, fmaxf(s[nj][0], s[nj][1]));
            mx1 = fmaxf(mx1, fmaxf(s[nj][2], s[nj][3]));
        }
        mx0 = fmaxf(mx0, __shfl_xor_sync(0xffffffffu, mx0, 1));
        mx0 = fmaxf(mx0, __shfl_xor_sync(0xffffffffu, mx0, 2));
        mx1 = fmaxf(mx1, __shfl_xor_sync(0xffffffffu, mx1, 1));
        mx1 = fmaxf(mx1, __shfl_xor_sync(0xffffffffu, mx1, 2));
        const float mn0 = fmaxf(m0r, mx0), mn1 = fmaxf(m1r, mx1);
        const float al0 = __expf(m0r - mn0), al1 = __expf(m1r - mn1);
        m0r = mn0; m1r = mn1;
        float sum0 = 0.0f, sum1 = 0.0f;
#pragma unroll
        for (int nj = 0; nj < 8; ++nj) {
            s[nj][0] = __expf(s[nj][0] - mn0);
            s[nj][1] = __expf(s[nj][1] - mn0);
            s[nj][2] = __expf(s[nj][2] - mn1);
            s[nj][3] = __expf(s[nj][3] - mn1);
            sum0 += s[nj][0] + s[nj][1];
            sum1 += s[nj][2] + s[nj][3];
            o[nj][0] *= al0; o[nj][1] *= al0;
            o[nj][2] *= al1; o[nj][3] *= al1;
        }
        sum0 += __shfl_xor_sync(0xffffffffu, sum0, 1);
        sum0 += __shfl_xor_sync(0xffffffffu, sum0, 2);
        sum1 += __shfl_xor_sync(0xffffffffu, sum1, 1);
        sum1 += __shfl_xor_sync(0xffffffffu, sum1, 2);
        l0 = l0 * al0 + sum0;
        l1 = l1 * al1 + sum1;

#pragma unroll
        for (int kc = 0; kc < 4; ++kc) {
            uint32_t ap[4];
            ap[0] = packh2(s[2 * kc][0], s[2 * kc][1]);
            ap[1] = packh2(s[2 * kc][2], s[2 * kc][3]);
            ap[2] = packh2(s[2 * kc + 1][0], s[2 * kc + 1][1]);
            ap[3] = packh2(s[2 * kc + 1][2], s[2 * kc + 1][3]);
#pragma unroll
            for (int nb = 0; nb < 4; ++nb) {
                uint32_t bt[4];
                LDSM4T(bt, vbb + voff + kc * (16 * RSB) + nb * 32);
                MMA_F16(o[2 * nb], ap, bt);
                MMA_F16(o[2 * nb + 1], ap, bt + 2);
            }
        }
    }

    const float inv0 = 1.0f / l0, inv1 = 1.0f / l1;
    const int row0 = q0 + wm + (lane >> 2);
    const size_t base0 = ((size_t)(b * SS) + row0) * DD + h * 64;
    const size_t base1 = base0 + 8 * DD;
#pragma unroll
    for (int nj = 0; nj < 8; ++nj) {
        const int d = nj * 8 + (lane & 3) * 2;
        {
            float v0 = o[nj][0] * inv0, v1 = o[nj][1] * inv0;
            __nv_bfloat16 h0 = __float2bfloat16(v0);
            __nv_bfloat16 h1 = __float2bfloat16(v1);
            ((uint32_t*)g_ahi)[(base0 + d) >> 1] =
                (uint32_t)*(unsigned short*)&h0 |
                ((uint32_t)*(unsigned short*)&h1 << 16);
            ((uint32_t*)g_alo)[(base0 + d) >> 1] =
                packbf2(v0 - __bfloat162float(h0), v1 - __bfloat162float(h1));
        }
        {
            float v0 = o[nj][2] * inv1, v1 = o[nj][3] * inv1;
            __nv_bfloat16 h0 = __float2bfloat16(v0);
            __nv_bfloat16 h1 = __float2bfloat16(v1);
            ((uint32_t*)g_ahi)[(base1 + d) >> 1] =
                (uint32_t)*(unsigned short*)&h0 |
                ((uint32_t)*(unsigned short*)&h1 << 16);
            ((uint32_t*)g_alo)[(base1 + d) >> 1] =
                packbf2(v0 - __bfloat162float(h0), v1 - __bfloat162float(h1));
        }
    }
}

// ---------------------------------------------------------------------------
// Launch
// ---------------------------------------------------------------------------
extern "C" void kernel_launch(void* const* d_in, const int* in_sizes, int n_in,
                              void* d_out, int out_size) {
    const float* x   = (const float*)d_in[0];
    const float* Wq  = (const float*)d_in[1];
    const float* Wk  = (const float*)d_in[2];
    const float* Wv  = (const float*)d_in[3];
    const float* Wo  = (const float*)d_in[4];
    const float* rel = (const float*)d_in[5];
    float* out = (float*)d_out;

    __nv_bfloat16 *pah, *pal, *pwh, *pwl, *pqh, *pql, *pkh, *pkl;
    __half* pvh;
    cudaGetSymbolAddress((void**)&pah, g_ahi);
    cudaGetSymbolAddress((void**)&pal, g_alo);
    cudaGetSymbolAddress((void**)&pwh, g_wthi);
    cudaGetSymbolAddress((void**)&pwl, g_wtlo);
    cudaGetSymbolAddress((void**)&pqh, g_qhi);
    cudaGetSymbolAddress((void**)&pql, g_qlo);
    cudaGetSymbolAddress((void**)&pkh, g_khi);
    cudaGetSymbolAddress((void**)&pkl, g_klo);
    cudaGetSymbolAddress((void**)&pvh, g_vh);

    static bool attr_set = false;
    if (!attr_set) {
        cudaFuncSetAttribute(tc_gemm<0>, cudaFuncAttributeMaxDynamicSharedMemorySize, GEMM_SMEM);
        cudaFuncSetAttribute(tc_gemm<3>, cudaFuncAttributeMaxDynamicSharedMemorySize, GEMM_SMEM);
        cudaFuncSetAttribute(attn_kernel, cudaFuncAttributeMaxDynamicSharedMemorySize, ATT_SMEM);
        attr_set = true;
    }

    bias_kernel<<<(HH * (2 * SS - 1) + 255) / 256, 256>>>(rel);

    const int n4 = BB * SS * DD / 4;
    split_kernel<<<(n4 + 255) / 256, 256>>>(x, pah, pal, n4);

    dim3 tg(32, 32, 4), tb(32, 8);
    splitT4_kernel<<<tg, tb>>>(Wq, Wk, Wv, Wo, pwh, pwl);

    // fused QKV: N = 3072
    dim3 gq(3 * DD / 128, (BB * SS) / 128);   // (24, 64)
    tc_gemm<3><<<gq, 256, GEMM_SMEM>>>(pah, pal, pwh, pwl,
                                       pqh, pql, pkh, pkl, pvh);

    dim3 ag(SS / 128, HH, BB);
    attn_kernel<<<ag, 256, ATT_SMEM>>>();

    // Wo GEMM (weights at section 3)
    dim3 go(DD / 128, (BB * SS) / 128);       // (8, 64)
    tc_gemm<0><<<go, 256, GEMM_SMEM>>>(pah, pal,
                                       pwh + 3 * DD * DD, pwl + 3 * DD * DD,
                                       out, nullptr, nullptr, nullptr, nullptr);
}